// round 3
// baseline (speedup 1.0000x reference)
#include <cuda_runtime.h>
#include <cstdint>

// Problem constants
#define BT_N   256      // B*T
#define RPT    512      // residues per (b,t)
#define DIM    256      // D
#define HID    128      // D/2
#define ROWS   64       // rows per CTA in kernel B
#define NTHR   256

// Scratch (device globals -- no allocation allowed)
__device__ float g_centroid[BT_N * 3];
__device__ float g_base[BT_N * DIM];

__device__ __forceinline__ float fast_tanh(float x) {
    float y;
    asm("tanh.approx.f32 %0, %1;" : "=f"(y) : "f"(x));
    return y;
}

__device__ __forceinline__ float gelu_tanh(float v) {
    float u = 0.7978845608028654f * (v + 0.044715f * v * v * v);
    return 0.5f * v * (1.0f + fast_tanh(u));
}

// Rotate v by normalized quaternion (w,x,y,z). Matches reference quat_to_matrix.
__device__ __forceinline__ void quat_rotate(float w, float x, float y, float z,
                                            float vx, float vy, float vz,
                                            float& ox, float& oy, float& oz) {
    float n = sqrtf(w * w + x * x + y * y + z * z);
    float inv = 1.0f / (n + 1e-8f);
    w *= inv; x *= inv; y *= inv; z *= inv;
    float xx = x * x, yy = y * y, zz = z * z;
    float xy = x * y, xz = x * z, yz = y * z;
    float wx = w * x, wy = w * y, wz = w * z;
    ox = (1.f - 2.f * (yy + zz)) * vx + 2.f * (xy - wz) * vy + 2.f * (xz + wy) * vz;
    oy = 2.f * (xy + wz) * vx + (1.f - 2.f * (xx + zz)) * vy + 2.f * (yz - wx) * vz;
    oz = 2.f * (xz - wy) * vx + 2.f * (yz + wx) * vy + (1.f - 2.f * (xx + yy)) * vz;
}

// ---------------------------------------------------------------------------
// Kernel A: per (b,t) -> centroid over R, and base = sf @ W1[0:256,:] + b1
// Grid: (BT_N), Block: 256
// ---------------------------------------------------------------------------
__global__ void __launch_bounds__(NTHR) precompute_kernel(
    const float* __restrict__ sf,     // (BT_N, 256)
    const float* __restrict__ trans,  // (BT_N, 512, 3)
    const float* __restrict__ W1,     // (259, 256)
    const float* __restrict__ b1)     // (256)
{
    __shared__ float sfs[DIM];
    __shared__ float red0[NTHR], red1[NTHR], red2[NTHR];

    int bt = blockIdx.x;
    int t  = threadIdx.x;

    sfs[t] = sf[bt * DIM + t];

    float sx = 0.f, sy = 0.f, sz = 0.f;
    #pragma unroll
    for (int r = t; r < RPT; r += NTHR) {
        const float* p = trans + ((size_t)bt * RPT + r) * 3;
        sx += p[0]; sy += p[1]; sz += p[2];
    }
    red0[t] = sx; red1[t] = sy; red2[t] = sz;
    __syncthreads();

    for (int s = NTHR / 2; s > 0; s >>= 1) {
        if (t < s) {
            red0[t] += red0[t + s];
            red1[t] += red1[t + s];
            red2[t] += red2[t + s];
        }
        __syncthreads();
    }
    if (t == 0) {
        g_centroid[bt * 3 + 0] = red0[0] * (1.0f / RPT);
        g_centroid[bt * 3 + 1] = red1[0] * (1.0f / RPT);
        g_centroid[bt * 3 + 2] = red2[0] * (1.0f / RPT);
    }

    // base[j] = b1[j] + sum_k sf[k] * W1[k, j]    (j = t, coalesced over W1 rows)
    float acc = b1[t];
    #pragma unroll 8
    for (int k = 0; k < DIM; k++) {
        acc += sfs[k] * W1[k * DIM + t];
    }
    g_base[bt * DIM + t] = acc;
}

// ---------------------------------------------------------------------------
// Kernel B: fused head. Grid: (RPT/ROWS=8, BT_N=256), Block: 256
// Dynamic smem layout (floats):
//   base_s[256] w1b[768] quat_s[256] lrp[192] b2_s[128] wt_s[384] wr_s[384]
//   btbr[16] h1[64*256] w2tile[2*32*128] h2[64*129]
// ---------------------------------------------------------------------------
#define SM_BASE  0
#define SM_W1B   256
#define SM_QUAT  1024
#define SM_LRP   1280
#define SM_B2    1472
#define SM_WT    1600
#define SM_WR    1984
#define SM_BTBR  2368
#define SM_H1    2384                     // 64*256 = 16384
#define SM_W2    (SM_H1 + 16384)          // 2*4096 = 8192
#define SM_H2    (SM_W2 + 8192)           // 64*129 = 8256
#define SM_TOTAL (SM_H2 + 8256)           // 35216 floats = 140864 bytes

__global__ void __launch_bounds__(NTHR, 1) head_kernel(
    const float* __restrict__ quat,   // (BT_N, 512, 4)
    const float* __restrict__ trans,  // (BT_N, 512, 3)
    const float* __restrict__ W1,     // (259, 256)
    const float* __restrict__ W2,     // (256, 128)
    const float* __restrict__ b2,     // (128)
    const float* __restrict__ Wt,     // (128, 3)
    const float* __restrict__ btp,    // (3)
    const float* __restrict__ Wr,     // (128, 3)
    const float* __restrict__ brp,    // (3)
    float* __restrict__ out)          // (BT_N, 512, 7)
{
    extern __shared__ float sm[];
    float* base_s = sm + SM_BASE;
    float* w1b    = sm + SM_W1B;
    float* quat_s = sm + SM_QUAT;
    float* lrp_s  = sm + SM_LRP;
    float* b2_s   = sm + SM_B2;
    float* wt_s   = sm + SM_WT;
    float* wr_s   = sm + SM_WR;
    float* btbr   = sm + SM_BTBR;
    float* h1s    = sm + SM_H1;
    float* w2s    = sm + SM_W2;
    float* h2s    = sm + SM_H2;

    const int t  = threadIdx.x;
    const int bt = blockIdx.y;
    const int r0 = blockIdx.x * ROWS;

    // ---- cooperative loads ----
    base_s[t] = g_base[bt * DIM + t];
    for (int i = t; i < 3 * DIM; i += NTHR) w1b[i] = W1[DIM * DIM + i];  // rows 256..258
    quat_s[t] = quat[((size_t)bt * RPT + r0) * 4 + t];                    // 64 rows * 4
    if (t < HID) b2_s[t] = b2[t];
    for (int i = t; i < HID * 3; i += NTHR) { wt_s[i] = Wt[i]; wr_s[i] = Wr[i]; }
    if (t < 3) { btbr[t] = btp[t]; btbr[4 + t] = brp[t]; }
    __syncthreads();

    // ---- per-row local_rel_pos (conjugate rotation) ----
    if (t < ROWS) {
        const float* tp = trans + ((size_t)bt * RPT + r0 + t) * 3;
        float cx = g_centroid[bt * 3 + 0];
        float cy = g_centroid[bt * 3 + 1];
        float cz = g_centroid[bt * 3 + 2];
        float vx = tp[0] - cx, vy = tp[1] - cy, vz = tp[2] - cz;
        float qw = quat_s[t * 4 + 0], qx = quat_s[t * 4 + 1];
        float qy = quat_s[t * 4 + 2], qz = quat_s[t * 4 + 3];
        float o0, o1, o2;
        quat_rotate(qw, -qx, -qy, -qz, vx, vy, vz, o0, o1, o2);
        lrp_s[t * 3 + 0] = o0;
        lrp_s[t * 3 + 1] = o1;
        lrp_s[t * 3 + 2] = o2;
    }
    __syncthreads();

    // ---- phase 1: h1 = gelu(base + lrp @ W1b). thread t owns column t ----
    {
        float b  = base_s[t];
        float w0 = w1b[t], w1c = w1b[DIM + t], w2c = w1b[2 * DIM + t];
        #pragma unroll 4
        for (int r = 0; r < ROWS; r++) {
            float l0 = lrp_s[r * 3 + 0], l1 = lrp_s[r * 3 + 1], l2 = lrp_s[r * 3 + 2];
            float v = b + l0 * w0 + l1 * w1c + l2 * w2c;
            h1s[r * DIM + t] = gelu_tanh(v);
        }
    }
    __syncthreads();

    // ---- phase 2: h2 = gelu(h1 @ W2 + b2), 64x128x256 register-tiled ----
    const int tx = t & 31;   // 32 column groups (4 cols each)
    const int ty = t >> 5;   // 8 row groups (8 rows each)

    float acc[8][4];
    #pragma unroll
    for (int i = 0; i < 8; i++)
        #pragma unroll
        for (int j = 0; j < 4; j++) acc[i][j] = 0.f;

    // prefetch tile 0
    #pragma unroll
    for (int i = 0; i < 16; i++) {
        int e = t + i * NTHR;                 // 0..4095 (row*128+col)
        w2s[e] = W2[e];
    }
    __syncthreads();

    #pragma unroll 1
    for (int kt = 0; kt < 8; kt++) {
        const float* cur = w2s + (kt & 1) * 4096;
        if (kt < 7) {
            float* nxt = w2s + ((kt + 1) & 1) * 4096;
            #pragma unroll
            for (int i = 0; i < 16; i++) {
                int e = t + i * NTHR;
                nxt[e] = W2[(kt + 1) * 4096 + e];
            }
        }
        #pragma unroll 8
        for (int kk = 0; kk < 32; kk++) {
            float4 wv = *reinterpret_cast<const float4*>(cur + kk * HID + tx * 4);
            #pragma unroll
            for (int i = 0; i < 8; i++) {
                float a = h1s[(ty * 8 + i) * DIM + kt * 32 + kk];
                acc[i][0] += a * wv.x;
                acc[i][1] += a * wv.y;
                acc[i][2] += a * wv.z;
                acc[i][3] += a * wv.w;
            }
        }
        __syncthreads();
    }

    // epilogue: bias + gelu -> h2s (row stride 129: conflict-free phase-3 reads)
    #pragma unroll
    for (int i = 0; i < 8; i++) {
        int row = ty * 8 + i;
        #pragma unroll
        for (int j = 0; j < 4; j++) {
            int col = tx * 4 + j;
            h2s[row * 129 + col] = gelu_tanh(acc[i][j] + b2_s[col]);
        }
    }
    __syncthreads();

    // ---- phase 3: heads + quaternion algebra + store ----
    if (t < ROWS) {
        float tv0 = btbr[0], tv1 = btbr[1], tv2 = btbr[2];
        float rv0 = btbr[4], rv1 = btbr[5], rv2 = btbr[6];
        const float* hrow = h2s + t * 129;
        #pragma unroll 4
        for (int k = 0; k < HID; k++) {
            float h = hrow[k];
            tv0 += h * wt_s[k * 3 + 0];
            tv1 += h * wt_s[k * 3 + 1];
            tv2 += h * wt_s[k * 3 + 2];
            rv0 += h * wr_s[k * 3 + 0];
            rv1 += h * wr_s[k * 3 + 1];
            rv2 += h * wr_s[k * 3 + 2];
        }
        rv0 *= 0.1f; rv1 *= 0.1f; rv2 *= 0.1f;

        float qw = quat_s[t * 4 + 0], qx = quat_s[t * 4 + 1];
        float qy = quat_s[t * 4 + 2], qz = quat_s[t * 4 + 3];

        // trans_vel = rotate(quat, tv)
        float wx, wy, wz;
        quat_rotate(qw, qx, qy, qz, tv0, tv1, tv2, wx, wy, wz);

        // quat_vel = 0.5 * quat_multiply(quat, [0, rv])
        float qvw = 0.5f * (-qx * rv0 - qy * rv1 - qz * rv2);
        float qvx = 0.5f * ( qw * rv0 + qy * rv2 - qz * rv1);
        float qvy = 0.5f * ( qw * rv1 - qx * rv2 + qz * rv0);
        float qvz = 0.5f * ( qw * rv2 + qx * rv1 - qy * rv0);

        float* o = out + ((size_t)bt * RPT + r0 + t) * 7;
        o[0] = qvw; o[1] = qvx; o[2] = qvy; o[3] = qvz;
        o[4] = wx;  o[5] = wy;  o[6] = wz;
    }
}

// ---------------------------------------------------------------------------
extern "C" void kernel_launch(void* const* d_in, const int* in_sizes, int n_in,
                              void* d_out, int out_size) {
    const float* sf    = (const float*)d_in[0];   // scalar_features (8,32,256)
    const float* quat  = (const float*)d_in[1];   // (8,32,512,4)
    const float* trans = (const float*)d_in[2];   // (8,32,512,3)
    const float* W1    = (const float*)d_in[3];   // (259,256)
    const float* b1    = (const float*)d_in[4];   // (256)
    const float* W2    = (const float*)d_in[5];   // (256,128)
    const float* b2    = (const float*)d_in[6];   // (128)
    const float* Wt    = (const float*)d_in[7];   // (128,3)
    const float* btp   = (const float*)d_in[8];   // (3)
    const float* Wr    = (const float*)d_in[9];   // (128,3)
    const float* brp   = (const float*)d_in[10];  // (3)
    float* out = (float*)d_out;

    size_t smem_bytes = (size_t)SM_TOTAL * sizeof(float);  // 140864
    cudaFuncSetAttribute(head_kernel, cudaFuncAttributeMaxDynamicSharedMemorySize,
                         (int)smem_bytes);

    precompute_kernel<<<BT_N, NTHR>>>(sf, trans, W1, b1);

    dim3 grid(RPT / ROWS, BT_N);   // (8, 256)
    head_kernel<<<grid, NTHR, smem_bytes>>>(quat, trans, W1, W2, b2,
                                            Wt, btp, Wr, brp, out);
}

// round 5
// speedup vs baseline: 1.3731x; 1.3731x over previous
#include <cuda_runtime.h>
#include <cstdint>

// Problem constants
#define BT_N   256      // B*T
#define RPT    512      // residues per (b,t)
#define DIM    256      // D
#define HID    128      // D/2
#define ROWS   64       // rows per CTA in kernel B
#define NTHR   256

// Scratch (device globals -- no allocation allowed)
__device__ float g_centroid[BT_N * 3];
__device__ float g_base[BT_N * DIM];

typedef unsigned long long ull;

__device__ __forceinline__ float fast_tanh(float x) {
    float y;
    asm("tanh.approx.f32 %0, %1;" : "=f"(y) : "f"(x));
    return y;
}

__device__ __forceinline__ float gelu_tanh(float v) {
    float u = 0.7978845608028654f * (v + 0.044715f * v * v * v);
    return 0.5f * v * (1.0f + fast_tanh(u));
}

// packed f32x2 helpers (Blackwell FFMA2 path)
__device__ __forceinline__ ull pack2(float x) {
    ull r;
    asm("mov.b64 %0, {%1, %1};" : "=l"(r) : "f"(x));
    return r;
}
__device__ __forceinline__ float2 unpack2(ull v) {
    float2 r;
    asm("mov.b64 {%0, %1}, %2;" : "=f"(r.x), "=f"(r.y) : "l"(v));
    return r;
}
__device__ __forceinline__ void ffma2(ull& d, ull a, ull b) {
    asm("fma.rn.f32x2 %0, %1, %2, %0;" : "+l"(d) : "l"(a), "l"(b));
}

// Rotate v by normalized quaternion (w,x,y,z). Matches reference quat_to_matrix.
__device__ __forceinline__ void quat_rotate(float w, float x, float y, float z,
                                            float vx, float vy, float vz,
                                            float& ox, float& oy, float& oz) {
    float n = sqrtf(w * w + x * x + y * y + z * z);
    float inv = 1.0f / (n + 1e-8f);
    w *= inv; x *= inv; y *= inv; z *= inv;
    float xx = x * x, yy = y * y, zz = z * z;
    float xy = x * y, xz = x * z, yz = y * z;
    float wx = w * x, wy = w * y, wz = w * z;
    ox = (1.f - 2.f * (yy + zz)) * vx + 2.f * (xy - wz) * vy + 2.f * (xz + wy) * vz;
    oy = 2.f * (xy + wz) * vx + (1.f - 2.f * (xx + zz)) * vy + 2.f * (yz - wx) * vz;
    oz = 2.f * (xz - wy) * vx + 2.f * (yz + wx) * vy + (1.f - 2.f * (xx + yy)) * vz;
}

// ---------------------------------------------------------------------------
// Kernel A: per (b,t) -> centroid over R, and base = sf @ W1[0:256,:] + b1
// ---------------------------------------------------------------------------
__global__ void __launch_bounds__(NTHR) precompute_kernel(
    const float* __restrict__ sf,     // (BT_N, 256)
    const float* __restrict__ trans,  // (BT_N, 512, 3)
    const float* __restrict__ W1,     // (259, 256)
    const float* __restrict__ b1)     // (256)
{
    __shared__ float sfs[DIM];
    __shared__ float red0[NTHR], red1[NTHR], red2[NTHR];

    int bt = blockIdx.x;
    int t  = threadIdx.x;

    sfs[t] = sf[bt * DIM + t];

    float sx = 0.f, sy = 0.f, sz = 0.f;
    #pragma unroll
    for (int r = t; r < RPT; r += NTHR) {
        const float* p = trans + ((size_t)bt * RPT + r) * 3;
        sx += p[0]; sy += p[1]; sz += p[2];
    }
    red0[t] = sx; red1[t] = sy; red2[t] = sz;
    __syncthreads();

    for (int s = NTHR / 2; s > 0; s >>= 1) {
        if (t < s) {
            red0[t] += red0[t + s];
            red1[t] += red1[t + s];
            red2[t] += red2[t + s];
        }
        __syncthreads();
    }
    if (t == 0) {
        g_centroid[bt * 3 + 0] = red0[0] * (1.0f / RPT);
        g_centroid[bt * 3 + 1] = red1[0] * (1.0f / RPT);
        g_centroid[bt * 3 + 2] = red2[0] * (1.0f / RPT);
    }

    float acc = b1[t];
    #pragma unroll 8
    for (int k = 0; k < DIM; k++) {
        acc += sfs[k] * W1[k * DIM + t];
    }
    g_base[bt * DIM + t] = acc;
}

// ---------------------------------------------------------------------------
// Kernel B: fused head. Grid: (8, 256), Block: 256, 2 CTAs/SM.
// Smem layout (floats):
//   misc[2384] | h1[64*256]=16384 (overlaid later by h2[64*132] + unused)
//   | w2 double buffer 2*4096 = 8192 (tail reused as output stage[448])
// total = 26960 floats = 107840 B
// ---------------------------------------------------------------------------
#define SM_BASE  0
#define SM_W1B   256
#define SM_QUAT  1024
#define SM_LRP   1280
#define SM_B2    1472
#define SM_WT    1600
#define SM_WR    1984
#define SM_BTBR  2368
#define SM_H1    2384                     // 16384 floats (union with h2: 64*132)
#define SM_W2    (SM_H1 + 16384)          // 8192 floats (union with out stage 448)
#define SM_TOTAL (SM_W2 + 8192)           // 26960 floats = 107840 bytes

#define H2_STRIDE 132

__global__ void __launch_bounds__(NTHR, 2) head_kernel(
    const float* __restrict__ quat,   // (BT_N, 512, 4)
    const float* __restrict__ trans,  // (BT_N, 512, 3)
    const float* __restrict__ W1,     // (259, 256)
    const float* __restrict__ W2,     // (256, 128)
    const float* __restrict__ b2,     // (128)
    const float* __restrict__ Wt,     // (128, 3)
    const float* __restrict__ btp,    // (3)
    const float* __restrict__ Wr,     // (128, 3)
    const float* __restrict__ brp,    // (3)
    float* __restrict__ out)          // (BT_N, 512, 7)
{
    extern __shared__ float sm[];
    float* base_s = sm + SM_BASE;
    float* w1b    = sm + SM_W1B;
    float* quat_s = sm + SM_QUAT;
    float* lrp_s  = sm + SM_LRP;
    float* b2_s   = sm + SM_B2;
    float* wt_s   = sm + SM_WT;
    float* wr_s   = sm + SM_WR;
    float* btbr   = sm + SM_BTBR;
    float* h1s    = sm + SM_H1;
    float* h2s    = sm + SM_H1;          // union: h1 dead after GEMM
    float* w2s    = sm + SM_W2;
    float* stage  = sm + SM_W2;          // union: w2 dead after GEMM

    const int t  = threadIdx.x;
    const int bt = blockIdx.y;
    const int r0 = blockIdx.x * ROWS;

    // ---- cooperative loads ----
    base_s[t] = g_base[bt * DIM + t];
    for (int i = t; i < 3 * DIM; i += NTHR) w1b[i] = W1[DIM * DIM + i];  // rows 256..258
    quat_s[t] = quat[((size_t)bt * RPT + r0) * 4 + t];                    // 64 rows * 4
    if (t < HID) b2_s[t] = b2[t];
    for (int i = t; i < HID * 3; i += NTHR) { wt_s[i] = Wt[i]; wr_s[i] = Wr[i]; }
    if (t < 3) { btbr[t] = btp[t]; btbr[4 + t] = brp[t]; }
    __syncthreads();

    // ---- per-row local_rel_pos (conjugate rotation) ----
    if (t < ROWS) {
        const float* tp = trans + ((size_t)bt * RPT + r0 + t) * 3;
        float cx = g_centroid[bt * 3 + 0];
        float cy = g_centroid[bt * 3 + 1];
        float cz = g_centroid[bt * 3 + 2];
        float vx = tp[0] - cx, vy = tp[1] - cy, vz = tp[2] - cz;
        float qw = quat_s[t * 4 + 0], qx = quat_s[t * 4 + 1];
        float qy = quat_s[t * 4 + 2], qz = quat_s[t * 4 + 3];
        float o0, o1, o2;
        quat_rotate(qw, -qx, -qy, -qz, vx, vy, vz, o0, o1, o2);
        lrp_s[t * 3 + 0] = o0;
        lrp_s[t * 3 + 1] = o1;
        lrp_s[t * 3 + 2] = o2;
    }
    __syncthreads();

    // ---- phase 1: h1 = gelu(base + lrp @ W1b). thread t owns column t ----
    {
        float b  = base_s[t];
        float w0 = w1b[t], w1c = w1b[DIM + t], w2c = w1b[2 * DIM + t];
        #pragma unroll 4
        for (int r = 0; r < ROWS; r++) {
            float l0 = lrp_s[r * 3 + 0], l1 = lrp_s[r * 3 + 1], l2 = lrp_s[r * 3 + 2];
            float v = b + l0 * w0 + l1 * w1c + l2 * w2c;
            h1s[r * DIM + t] = gelu_tanh(v);
        }
    }

    // prefetch W2 tile 0 (no sync needed yet: w2s untouched so far)
    #pragma unroll
    for (int i = 0; i < 16; i++) {
        int e = t + i * NTHR;
        w2s[e] = W2[e];
    }
    __syncthreads();

    // ---- phase 2: h2 = gelu(h1 @ W2 + b2), 64x128x256 with packed FFMA2 ----
    const int tx = t & 31;   // 32 column groups (4 cols each)
    const int ty = t >> 5;   // 8 row groups (8 rows each)

    ull acc01[8], acc23[8];
    {
        ull z = pack2(0.0f);
        #pragma unroll
        for (int i = 0; i < 8; i++) { acc01[i] = z; acc23[i] = z; }
    }

    #pragma unroll 1
    for (int kt = 0; kt < 8; kt++) {
        const float* cur = w2s + (kt & 1) * 4096;
        if (kt < 7) {
            float* nxt = w2s + ((kt + 1) & 1) * 4096;
            #pragma unroll
            for (int i = 0; i < 16; i++) {
                int e = t + i * NTHR;
                nxt[e] = W2[(kt + 1) * 4096 + e];
            }
        }
        const float* h1p = h1s + (ty * 8) * DIM + kt * 32;
        #pragma unroll 4
        for (int kk = 0; kk < 32; kk += 2) {
            float2 a[8];
            #pragma unroll
            for (int i = 0; i < 8; i++)
                a[i] = *reinterpret_cast<const float2*>(h1p + i * DIM + kk);
            ulonglong2 wv0 = *reinterpret_cast<const ulonglong2*>(cur + kk * HID + tx * 4);
            ulonglong2 wv1 = *reinterpret_cast<const ulonglong2*>(cur + (kk + 1) * HID + tx * 4);
            #pragma unroll
            for (int i = 0; i < 8; i++) {
                ull ax = pack2(a[i].x);
                ull ay = pack2(a[i].y);
                ffma2(acc01[i], ax, wv0.x);
                ffma2(acc23[i], ax, wv0.y);
                ffma2(acc01[i], ay, wv1.x);
                ffma2(acc23[i], ay, wv1.y);
            }
        }
        __syncthreads();
    }

    // epilogue: bias + gelu -> h2s (stride 132, overlaying h1; all reads done)
    {
        float b0 = b2_s[tx * 4 + 0], b1c = b2_s[tx * 4 + 1];
        float b2c = b2_s[tx * 4 + 2], b3 = b2_s[tx * 4 + 3];
        #pragma unroll
        for (int i = 0; i < 8; i++) {
            int row = ty * 8 + i;
            float2 v01 = unpack2(acc01[i]);
            float2 v23 = unpack2(acc23[i]);
            float4 g;
            g.x = gelu_tanh(v01.x + b0);
            g.y = gelu_tanh(v01.y + b1c);
            g.z = gelu_tanh(v23.x + b2c);
            g.w = gelu_tanh(v23.y + b3);
            *reinterpret_cast<float4*>(h2s + row * H2_STRIDE + tx * 4) = g;
        }
    }
    __syncthreads();

    // ---- phase 3: heads, 4 threads per row (interleaved k), shfl reduce ----
    {
        const int row = t >> 2;
        const int sub = t & 3;
        const float* hrow = h2s + row * H2_STRIDE;
        float s0 = 0.f, s1 = 0.f, s2 = 0.f, s3 = 0.f, s4 = 0.f, s5 = 0.f;
        #pragma unroll 8
        for (int j = 0; j < 32; j++) {
            int k = sub + 4 * j;
            float h = hrow[k];
            s0 += h * wt_s[k * 3 + 0];
            s1 += h * wt_s[k * 3 + 1];
            s2 += h * wt_s[k * 3 + 2];
            s3 += h * wr_s[k * 3 + 0];
            s4 += h * wr_s[k * 3 + 1];
            s5 += h * wr_s[k * 3 + 2];
        }
        #pragma unroll
        for (int m = 1; m <= 2; m <<= 1) {
            s0 += __shfl_xor_sync(0xffffffff, s0, m);
            s1 += __shfl_xor_sync(0xffffffff, s1, m);
            s2 += __shfl_xor_sync(0xffffffff, s2, m);
            s3 += __shfl_xor_sync(0xffffffff, s3, m);
            s4 += __shfl_xor_sync(0xffffffff, s4, m);
            s5 += __shfl_xor_sync(0xffffffff, s5, m);
        }
        if (sub == 0) {
            float tv0 = s0 + btbr[0], tv1 = s1 + btbr[1], tv2 = s2 + btbr[2];
            float rv0 = (s3 + btbr[4]) * 0.1f;
            float rv1 = (s4 + btbr[5]) * 0.1f;
            float rv2 = (s5 + btbr[6]) * 0.1f;

            float qw = quat_s[row * 4 + 0], qx = quat_s[row * 4 + 1];
            float qy = quat_s[row * 4 + 2], qz = quat_s[row * 4 + 3];

            float wx, wy, wz;
            quat_rotate(qw, qx, qy, qz, tv0, tv1, tv2, wx, wy, wz);

            float qvw = 0.5f * (-qx * rv0 - qy * rv1 - qz * rv2);
            float qvx = 0.5f * ( qw * rv0 + qy * rv2 - qz * rv1);
            float qvy = 0.5f * ( qw * rv1 - qx * rv2 + qz * rv0);
            float qvz = 0.5f * ( qw * rv2 + qx * rv1 - qy * rv0);

            float* st = stage + row * 7;
            st[0] = qvw; st[1] = qvx; st[2] = qvy; st[3] = qvz;
            st[4] = wx;  st[5] = wy;  st[6] = wz;
        }
    }
    __syncthreads();

    // coalesced output store: 448 contiguous floats per CTA
    {
        float* obase = out + ((size_t)bt * RPT + r0) * 7;
        if (t < 192) {
            obase[t]       = stage[t];
            obase[t + 256] = stage[t + 256];
        } else {
            obase[t] = stage[t];
        }
    }
}

// ---------------------------------------------------------------------------
extern "C" void kernel_launch(void* const* d_in, const int* in_sizes, int n_in,
                              void* d_out, int out_size) {
    const float* sf    = (const float*)d_in[0];   // scalar_features (8,32,256)
    const float* quat  = (const float*)d_in[1];   // (8,32,512,4)
    const float* trans = (const float*)d_in[2];   // (8,32,512,3)
    const float* W1    = (const float*)d_in[3];   // (259,256)
    const float* b1    = (const float*)d_in[4];   // (256)
    const float* W2    = (const float*)d_in[5];   // (256,128)
    const float* b2    = (const float*)d_in[6];   // (128)
    const float* Wt    = (const float*)d_in[7];   // (128,3)
    const float* btp   = (const float*)d_in[8];   // (3)
    const float* Wr    = (const float*)d_in[9];   // (128,3)
    const float* brp   = (const float*)d_in[10];  // (3)
    float* out = (float*)d_out;

    size_t smem_bytes = (size_t)SM_TOTAL * sizeof(float);  // 107840
    cudaFuncSetAttribute(head_kernel, cudaFuncAttributeMaxDynamicSharedMemorySize,
                         (int)smem_bytes);

    precompute_kernel<<<BT_N, NTHR>>>(sf, trans, W1, b1);

    dim3 grid(RPT / ROWS, BT_N);   // (8, 256)
    head_kernel<<<grid, NTHR, smem_bytes>>>(quat, trans, W1, W2, b2,
                                            Wt, btp, Wr, brp, out);
}

// round 7
// speedup vs baseline: 2.2929x; 1.6698x over previous
#include <cuda_runtime.h>
#include <cuda_bf16.h>
#include <cstdint>

// Problem constants
#define BT_N   256      // B*T
#define RPT    512
#define DIM    256      // D (= K of GEMM2)
#define HID    128      // D/2 (= N of GEMM2)
#define MROWS  128      // rows per CTA (= M of GEMM2 tile)
#define NTHR   256

// Scratch (device globals -- no allocation allowed)
__device__ float g_centroid[BT_N * 3];
__device__ float g_base[BT_N * DIM];
// W2^T bf16 hi/lo images: [n=128][kword=128] (k-major, 2 bf16 per word)
__device__ __align__(16) unsigned g_Bhi[16384];
__device__ __align__(16) unsigned g_Blo[16384];

// ---- smem word-layout (word = 4 bytes) ----
// A row stride 132 words (264 bf16; 132 % 32 == 4 -> conflict-free ldmatrix)
#define A_STRIDE_W 132
#define A_HI_W     0
#define A_LO_W     16896                  // 128*132
#define B_STRIDE_W 68                     // 136 bf16 per row (68 % 32 == 4)
#define B_HI_W     33792
#define B_LO_W     42496                  // 33792 + 128*68
#define MISC_W     51200                  // 42496 + 8704
// misc float offsets (within misc region)
#define MF_BASE 0
#define MF_W1B  256
#define MF_QUAT 1024
#define MF_LRP  1536
#define MF_B2   1920
#define MF_WT   2048
#define MF_WR   2432
#define MF_BTBR 2816
#define MF_STG  2824
#define MISC_FLOATS 3720
#define SMEM_BYTES ((MISC_W + MISC_FLOATS) * 4)     // 219680

// ---------------- helpers ----------------
__device__ __forceinline__ uint32_t smem_u32(const void* p) {
    uint32_t a;
    asm("{ .reg .u64 t; cvta.to.shared.u64 t, %1; cvt.u32.u64 %0, t; }" : "=r"(a) : "l"(p));
    return a;
}
__device__ __forceinline__ float fast_tanh(float x) {
    float y; asm("tanh.approx.f32 %0, %1;" : "=f"(y) : "f"(x)); return y;
}
__device__ __forceinline__ float gelu_tanh(float v) {
    float u = 0.7978845608028654f * (v + 0.044715f * v * v * v);
    return 0.5f * v * (1.0f + fast_tanh(u));
}
// hi = truncate-to-bf16 (top 16 bits), lo = rn-bf16 of remainder; packs 2 values.
__device__ __forceinline__ void split_pair(float v0, float v1,
                                           unsigned& hi_word, unsigned& lo_word) {
    unsigned u0 = __float_as_uint(v0), u1 = __float_as_uint(v1);
    hi_word = __byte_perm(u0, u1, 0x7632);           // {u0.hi16, u1.hi16}
    float l0 = v0 - __uint_as_float(u0 & 0xFFFF0000u);
    float l1 = v1 - __uint_as_float(u1 & 0xFFFF0000u);
    asm("cvt.rn.satfinite.bf16x2.f32 %0, %1, %2;" : "=r"(lo_word) : "f"(l1), "f"(l0));
}
__device__ __forceinline__ void quat_rotate(float w, float x, float y, float z,
                                            float vx, float vy, float vz,
                                            float& ox, float& oy, float& oz) {
    float n = sqrtf(w * w + x * x + y * y + z * z);
    float inv = 1.0f / (n + 1e-8f);
    w *= inv; x *= inv; y *= inv; z *= inv;
    float xx = x * x, yy = y * y, zz = z * z;
    float xy = x * y, xz = x * z, yz = y * z;
    float wx = w * x, wy = w * y, wz = w * z;
    ox = (1.f - 2.f * (yy + zz)) * vx + 2.f * (xy - wz) * vy + 2.f * (xz + wy) * vz;
    oy = 2.f * (xy + wz) * vx + (1.f - 2.f * (xx + zz)) * vy + 2.f * (yz - wx) * vz;
    oz = 2.f * (xz - wy) * vx + 2.f * (yz + wx) * vy + (1.f - 2.f * (xx + yy)) * vz;
}
__device__ __forceinline__ void ldsm_x4(unsigned* r, uint32_t addr) {
    asm volatile("ldmatrix.sync.aligned.m8n8.x4.shared.b16 {%0,%1,%2,%3}, [%4];"
                 : "=r"(r[0]), "=r"(r[1]), "=r"(r[2]), "=r"(r[3]) : "r"(addr));
}
__device__ __forceinline__ void ldsm_x2(unsigned* r, uint32_t addr) {
    asm volatile("ldmatrix.sync.aligned.m8n8.x2.shared.b16 {%0,%1}, [%2];"
                 : "=r"(r[0]), "=r"(r[1]) : "r"(addr));
}
__device__ __forceinline__ void mma16816(float* c, const unsigned* a, const unsigned* b) {
    asm volatile("mma.sync.aligned.m16n8k16.row.col.f32.bf16.bf16.f32 "
                 "{%0,%1,%2,%3}, {%4,%5,%6,%7}, {%8,%9}, {%0,%1,%2,%3};"
                 : "+f"(c[0]), "+f"(c[1]), "+f"(c[2]), "+f"(c[3])
                 : "r"(a[0]), "r"(a[1]), "r"(a[2]), "r"(a[3]), "r"(b[0]), "r"(b[1]));
}

// ---------------------------------------------------------------------------
// Kernel A: per (b,t) centroid + base = sf @ W1[0:256,:] + b1
// ---------------------------------------------------------------------------
__global__ void __launch_bounds__(NTHR) precompute_kernel(
    const float* __restrict__ sf, const float* __restrict__ trans,
    const float* __restrict__ W1, const float* __restrict__ b1)
{
    __shared__ float sfs[DIM];
    __shared__ float red0[NTHR], red1[NTHR], red2[NTHR];
    int bt = blockIdx.x, t = threadIdx.x;
    sfs[t] = sf[bt * DIM + t];

    float sx = 0.f, sy = 0.f, sz = 0.f;
    for (int r = t; r < RPT; r += NTHR) {
        const float* p = trans + ((size_t)bt * RPT + r) * 3;
        sx += p[0]; sy += p[1]; sz += p[2];
    }
    red0[t] = sx; red1[t] = sy; red2[t] = sz;
    __syncthreads();
    for (int s = NTHR / 2; s > 0; s >>= 1) {
        if (t < s) { red0[t] += red0[t+s]; red1[t] += red1[t+s]; red2[t] += red2[t+s]; }
        __syncthreads();
    }
    if (t == 0) {
        g_centroid[bt*3+0] = red0[0] * (1.0f/RPT);
        g_centroid[bt*3+1] = red1[0] * (1.0f/RPT);
        g_centroid[bt*3+2] = red2[0] * (1.0f/RPT);
    }
    float acc = b1[t];
    #pragma unroll 8
    for (int k = 0; k < DIM; k++) acc += sfs[k] * W1[k * DIM + t];
    g_base[bt * DIM + t] = acc;
}

// ---------------------------------------------------------------------------
// Kernel W: one-time W2 -> W2^T bf16 hi/lo images [n][kword]
// ---------------------------------------------------------------------------
__global__ void __launch_bounds__(NTHR) convert_w2_kernel(const float* __restrict__ W2)
{
    int idx = blockIdx.x * NTHR + threadIdx.x;  // 16384
    int n  = idx >> 7;
    int kp = idx & 127;
    int k0 = kp * 2;
    float w0 = W2[k0 * HID + n];
    float w1 = W2[(k0 + 1) * HID + n];
    unsigned hw, lw;
    split_pair(w0, w1, hw, lw);
    g_Bhi[n * 128 + kp] = hw;
    g_Blo[n * 128 + kp] = lw;
}

// ---------------------------------------------------------------------------
// Kernel B: fused head, GEMM2 via mma.sync bf16x3. Grid (4,256), 256 thr, 1 CTA/SM.
// ---------------------------------------------------------------------------
__global__ void __launch_bounds__(NTHR, 1) head_kernel(
    const float* __restrict__ quat, const float* __restrict__ trans,
    const float* __restrict__ W1, const float* __restrict__ b2,
    const float* __restrict__ Wt, const float* __restrict__ btp,
    const float* __restrict__ Wr, const float* __restrict__ brp,
    float* __restrict__ out)
{
    extern __shared__ char smp[];
    unsigned* smw = (unsigned*)smp;
    uint32_t sb = smem_u32(smp);

    float* misc   = (float*)smp + MISC_W;
    float* base_s = misc + MF_BASE;
    float* w1b    = misc + MF_W1B;
    float* quat_s = misc + MF_QUAT;
    float* lrp_s  = misc + MF_LRP;
    float* b2_s   = misc + MF_B2;
    float* wt_s   = misc + MF_WT;
    float* wr_s   = misc + MF_WR;
    float* btbr   = misc + MF_BTBR;
    float* stage  = misc + MF_STG;
    float* h2s    = (float*)smp;              // overlays A region after GEMM

    const int t    = threadIdx.x;
    const int lane = t & 31;
    const int wid  = t >> 5;
    const int bt   = blockIdx.y;
    const int r0   = blockIdx.x * MROWS;

    // ---- cooperative loads ----
    base_s[t] = g_base[bt * DIM + t];
    for (int i = t; i < 3 * DIM; i += NTHR) w1b[i] = W1[DIM * DIM + i];
    for (int i = t; i < MROWS * 4; i += NTHR)
        quat_s[i] = quat[((size_t)bt * RPT + r0) * 4 + i];
    if (t < HID) b2_s[t] = b2[t];
    for (int i = t; i < HID * 3; i += NTHR) { wt_s[i] = Wt[i]; wr_s[i] = Wr[i]; }
    if (t < 3) { btbr[t] = btp[t]; btbr[4 + t] = brp[t]; }
    __syncthreads();

    // ---- local_rel_pos (conjugate rotation), 128 rows ----
    if (t < MROWS) {
        const float* tp = trans + ((size_t)bt * RPT + r0 + t) * 3;
        float vx = tp[0] - g_centroid[bt*3+0];
        float vy = tp[1] - g_centroid[bt*3+1];
        float vz = tp[2] - g_centroid[bt*3+2];
        float qw = quat_s[t*4+0], qx = quat_s[t*4+1], qy = quat_s[t*4+2], qz = quat_s[t*4+3];
        float o0, o1, o2;
        quat_rotate(qw, -qx, -qy, -qz, vx, vy, vz, o0, o1, o2);
        lrp_s[t*3+0] = o0; lrp_s[t*3+1] = o1; lrp_s[t*3+2] = o2;
    }
    __syncthreads();

    // ---- phase 1: h1 = gelu(base + lrp @ W1b) -> bf16 hi/lo into A images ----
    {
        int kp = t & 127, rh = t >> 7;
        int k0 = kp * 2;
        float b0 = base_s[k0], b1v = base_s[k0+1];
        float wa0 = w1b[k0],   wb0 = w1b[256+k0],   wc0 = w1b[512+k0];
        float wa1 = w1b[k0+1], wb1 = w1b[256+k0+1], wc1 = w1b[512+k0+1];
        #pragma unroll 4
        for (int r = 0; r < 64; r++) {
            int row = rh * 64 + r;
            float l0 = lrp_s[row*3+0], l1 = lrp_s[row*3+1], l2 = lrp_s[row*3+2];
            float v0 = gelu_tanh(b0  + l0*wa0 + l1*wb0 + l2*wc0);
            float v1 = gelu_tanh(b1v + l0*wa1 + l1*wb1 + l2*wc1);
            unsigned hw, lw;
            split_pair(v0, v1, hw, lw);
            int w = row * A_STRIDE_W + kp;
            smw[A_HI_W + w] = hw;
            smw[A_LO_W + w] = lw;
        }
    }

    // ---- GEMM2: C[128x128] = h1 @ W2, bf16x3 via mma.sync ----
    const int wm = wid >> 2;          // 0..1 (m half)
    const int wn = wid & 3;           // 0..3 (n quarter)

    float acc[4][4][4];
    #pragma unroll
    for (int i = 0; i < 4; i++)
        #pragma unroll
        for (int j = 0; j < 4; j++)
            #pragma unroll
            for (int k = 0; k < 4; k++) acc[i][j][k] = 0.f;

    // per-lane ldmatrix base addresses (bytes)
    uint32_t aAddrHi = sb + ((uint32_t)(wm*64 + (lane & 15)) * A_STRIDE_W
                             + ((lane >> 4) << 2)) * 4u;
    uint32_t aAddrLo = aAddrHi + A_LO_W * 4u;
    uint32_t bAddrHi = sb + (B_HI_W + (uint32_t)(wn*32 + (lane & 7)) * B_STRIDE_W
                             + (((lane >> 3) & 1) << 2)) * 4u;
    uint32_t bAddrLo = bAddrHi + (B_LO_W - B_HI_W) * 4u;

    #pragma unroll 1
    for (int h = 0; h < 2; h++) {
        if (h) __syncthreads();       // all h=0 MMAs done before B overwrite
        // copy pre-swizzled B k-half into smem (hi + lo)
        #pragma unroll
        for (int i = t; i < 2048; i += NTHR) {
            int n = i >> 4, s = i & 15;
            uint4 vh = ((const uint4*)g_Bhi)[n*32 + h*16 + s];
            uint4 vl = ((const uint4*)g_Blo)[n*32 + h*16 + s];
            *(uint4*)(smp + (size_t)(B_HI_W + n*B_STRIDE_W + s*4) * 4) = vh;
            *(uint4*)(smp + (size_t)(B_LO_W + n*B_STRIDE_W + s*4) * 4) = vl;
        }
        __syncthreads();              // (h=0: also covers phase-1 A writes)

        uint32_t aK = (uint32_t)h * 256u;   // 64 words
        #pragma unroll 2
        for (int ks = 0; ks < 8; ks++) {
            unsigned ah[4][4], al[4][4], bh[4][2], bl[4][2];
            #pragma unroll
            for (int mt = 0; mt < 4; mt++) {
                uint32_t off = (uint32_t)mt * (16 * A_STRIDE_W * 4) + aK + (uint32_t)ks * 32u;
                ldsm_x4(ah[mt], aAddrHi + off);
                ldsm_x4(al[mt], aAddrLo + off);
            }
            #pragma unroll
            for (int nt = 0; nt < 4; nt++) {
                uint32_t off = (uint32_t)nt * (8 * B_STRIDE_W * 4) + (uint32_t)ks * 32u;
                ldsm_x2(bh[nt], bAddrHi + off);
                ldsm_x2(bl[nt], bAddrLo + off);
            }
            #pragma unroll
            for (int mt = 0; mt < 4; mt++)
                #pragma unroll
                for (int nt = 0; nt < 4; nt++) {
                    mma16816(acc[mt][nt], ah[mt], bh[nt]);
                    mma16816(acc[mt][nt], ah[mt], bl[nt]);
                    mma16816(acc[mt][nt], al[mt], bh[nt]);
                }
        }
    }
    __syncthreads();                   // all A reads done before h2 overlay

    // ---- epilogue: bias + gelu -> h2s (stride 132 words, overlays A) ----
    {
        const int q = lane & 3, g = lane >> 2;
        #pragma unroll
        for (int mt = 0; mt < 4; mt++) {
            int row = wm*64 + mt*16 + g;
            #pragma unroll
            for (int nt = 0; nt < 4; nt++) {
                int col = wn*32 + nt*8 + 2*q;
                float bA = b2_s[col], bB = b2_s[col+1];
                float2 v0; v0.x = gelu_tanh(acc[mt][nt][0] + bA);
                           v0.y = gelu_tanh(acc[mt][nt][1] + bB);
                float2 v1; v1.x = gelu_tanh(acc[mt][nt][2] + bA);
                           v1.y = gelu_tanh(acc[mt][nt][3] + bB);
                *(float2*)&h2s[row * A_STRIDE_W + col]       = v0;
                *(float2*)&h2s[(row+8) * A_STRIDE_W + col]   = v1;
            }
        }
    }
    __syncthreads();

    // ---- phase 3: heads, 2 threads/row, shfl reduce ----
    {
        const int row = t >> 1, sub = t & 1;
        const float* hrow = h2s + row * A_STRIDE_W;
        float s0=0.f,s1=0.f,s2=0.f,s3=0.f,s4=0.f,s5=0.f;
        #pragma unroll 8
        for (int j = 0; j < 64; j++) {
            int k = 2 * j + sub;
            float hv = hrow[k];
            s0 += hv * wt_s[k*3+0]; s1 += hv * wt_s[k*3+1]; s2 += hv * wt_s[k*3+2];
            s3 += hv * wr_s[k*3+0]; s4 += hv * wr_s[k*3+1]; s5 += hv * wr_s[k*3+2];
        }
        s0 += __shfl_xor_sync(0xffffffff, s0, 1);
        s1 += __shfl_xor_sync(0xffffffff, s1, 1);
        s2 += __shfl_xor_sync(0xffffffff, s2, 1);
        s3 += __shfl_xor_sync(0xffffffff, s3, 1);
        s4 += __shfl_xor_sync(0xffffffff, s4, 1);
        s5 += __shfl_xor_sync(0xffffffff, s5, 1);
        if (sub == 0) {
            float tv0 = s0 + btbr[0], tv1 = s1 + btbr[1], tv2 = s2 + btbr[2];
            float rv0 = (s3 + btbr[4]) * 0.1f;
            float rv1 = (s4 + btbr[5]) * 0.1f;
            float rv2 = (s5 + btbr[6]) * 0.1f;
            float qw = quat_s[row*4+0], qx = quat_s[row*4+1];
            float qy = quat_s[row*4+2], qz = quat_s[row*4+3];
            float wx, wy, wz;
            quat_rotate(qw, qx, qy, qz, tv0, tv1, tv2, wx, wy, wz);
            float qvw = 0.5f * (-qx*rv0 - qy*rv1 - qz*rv2);
            float qvx = 0.5f * ( qw*rv0 + qy*rv2 - qz*rv1);
            float qvy = 0.5f * ( qw*rv1 - qx*rv2 + qz*rv0);
            float qvz = 0.5f * ( qw*rv2 + qx*rv1 - qy*rv0);
            float* st = stage + row * 7;
            st[0]=qvw; st[1]=qvx; st[2]=qvy; st[3]=qvz; st[4]=wx; st[5]=wy; st[6]=wz;
        }
    }
    __syncthreads();

    // coalesced store: 896 contiguous floats per CTA
    {
        float* obase = out + ((size_t)bt * RPT + r0) * 7;
        #pragma unroll
        for (int i = 0; i < 3; i++) obase[t + i * NTHR] = stage[t + i * NTHR];
        if (t < 128) obase[t + 768] = stage[t + 768];
    }
}

// ---------------------------------------------------------------------------
extern "C" void kernel_launch(void* const* d_in, const int* in_sizes, int n_in,
                              void* d_out, int out_size) {
    const float* sf    = (const float*)d_in[0];
    const float* quat  = (const float*)d_in[1];
    const float* trans = (const float*)d_in[2];
    const float* W1    = (const float*)d_in[3];
    const float* b1    = (const float*)d_in[4];
    const float* W2    = (const float*)d_in[5];
    const float* b2    = (const float*)d_in[6];
    const float* Wt    = (const float*)d_in[7];
    const float* btp   = (const float*)d_in[8];
    const float* Wr    = (const float*)d_in[9];
    const float* brp   = (const float*)d_in[10];
    float* out = (float*)d_out;

    cudaFuncSetAttribute(head_kernel, cudaFuncAttributeMaxDynamicSharedMemorySize,
                         SMEM_BYTES);

    precompute_kernel<<<BT_N, NTHR>>>(sf, trans, W1, b1);
    convert_w2_kernel<<<64, NTHR>>>(W2);

    dim3 grid(RPT / MROWS, BT_N);    // (4, 256)
    head_kernel<<<grid, NTHR, SMEM_BYTES>>>(quat, trans, W1, b2, Wt, btp, Wr, brp, out);
}

// round 8
// speedup vs baseline: 2.4000x; 1.0467x over previous
#include <cuda_runtime.h>
#include <cuda_bf16.h>
#include <cstdint>

// Problem constants
#define BT_N   256      // B*T
#define RPT    512
#define DIM    256      // D (= K of GEMM2)
#define HID    128      // D/2 (= N of GEMM2)
#define MROWS  128      // rows per CTA (= M of GEMM2 tile)
#define NTHR   256

// Scratch (device globals -- no allocation allowed)
__device__ float g_centroid[BT_N * 3];
__device__ float g_base[BT_N * DIM];
// W2^T bf16 hi/lo images: [n=128][kword=128] (k-major, 2 bf16 per word)
__device__ __align__(16) unsigned g_Bhi[16384];
__device__ __align__(16) unsigned g_Blo[16384];

// ---- smem word-layout (word = 4 bytes) ----
#define A_STRIDE_W 132
#define A_HI_W     0
#define A_LO_W     16896                  // 128*132
#define B_STRIDE_W 68                     // 68 % 32 == 4 -> conflict-free ldmatrix
#define B_HI_W     33792
#define B_LO_W     42496                  // 33792 + 128*68
#define MISC_W     51200                  // 42496 + 8704
// misc float offsets (within misc region)
#define MF_BASE 0
#define MF_W1B  256
#define MF_QUAT 1024
#define MF_LRP  1536
#define MF_B2   1920
#define MF_WT   2048
#define MF_WR   2432
#define MF_BTBR 2816
#define MF_STG  2824
#define MISC_FLOATS 3720
#define SMEM_BYTES ((MISC_W + MISC_FLOATS) * 4)     // 219680

// ---------------- helpers ----------------
__device__ __forceinline__ uint32_t smem_u32(const void* p) {
    uint32_t a;
    asm("{ .reg .u64 t; cvta.to.shared.u64 t, %1; cvt.u32.u64 %0, t; }" : "=r"(a) : "l"(p));
    return a;
}
__device__ __forceinline__ void cp_async16(uint32_t dst, const void* src) {
    asm volatile("cp.async.cg.shared.global [%0], [%1], 16;" :: "r"(dst), "l"(src) : "memory");
}
__device__ __forceinline__ float fast_tanh(float x) {
    float y; asm("tanh.approx.f32 %0, %1;" : "=f"(y) : "f"(x)); return y;
}
__device__ __forceinline__ float gelu_tanh(float v) {
    float u = 0.7978845608028654f * (v + 0.044715f * v * v * v);
    return 0.5f * v * (1.0f + fast_tanh(u));
}
// hi = truncate-to-bf16 (top 16 bits), lo = rn-bf16 of remainder; packs 2 values.
__device__ __forceinline__ void split_pair(float v0, float v1,
                                           unsigned& hi_word, unsigned& lo_word) {
    unsigned u0 = __float_as_uint(v0), u1 = __float_as_uint(v1);
    hi_word = __byte_perm(u0, u1, 0x7632);           // {u0.hi16, u1.hi16}
    float l0 = v0 - __uint_as_float(u0 & 0xFFFF0000u);
    float l1 = v1 - __uint_as_float(u1 & 0xFFFF0000u);
    asm("cvt.rn.satfinite.bf16x2.f32 %0, %1, %2;" : "=r"(lo_word) : "f"(l1), "f"(l0));
}
__device__ __forceinline__ void quat_rotate(float w, float x, float y, float z,
                                            float vx, float vy, float vz,
                                            float& ox, float& oy, float& oz) {
    float n = sqrtf(w * w + x * x + y * y + z * z);
    float inv = 1.0f / (n + 1e-8f);
    w *= inv; x *= inv; y *= inv; z *= inv;
    float xx = x * x, yy = y * y, zz = z * z;
    float xy = x * y, xz = x * z, yz = y * z;
    float wx = w * x, wy = w * y, wz = w * z;
    ox = (1.f - 2.f * (yy + zz)) * vx + 2.f * (xy - wz) * vy + 2.f * (xz + wy) * vz;
    oy = 2.f * (xy + wz) * vx + (1.f - 2.f * (xx + zz)) * vy + 2.f * (yz - wx) * vz;
    oz = 2.f * (xz - wy) * vx + 2.f * (yz + wx) * vy + (1.f - 2.f * (xx + yy)) * vz;
}
__device__ __forceinline__ void ldsm_x4(unsigned* r, uint32_t addr) {
    asm volatile("ldmatrix.sync.aligned.m8n8.x4.shared.b16 {%0,%1,%2,%3}, [%4];"
                 : "=r"(r[0]), "=r"(r[1]), "=r"(r[2]), "=r"(r[3]) : "r"(addr));
}
__device__ __forceinline__ void mma16816(float* c, const unsigned* a, const unsigned* b) {
    asm volatile("mma.sync.aligned.m16n8k16.row.col.f32.bf16.bf16.f32 "
                 "{%0,%1,%2,%3}, {%4,%5,%6,%7}, {%8,%9}, {%0,%1,%2,%3};"
                 : "+f"(c[0]), "+f"(c[1]), "+f"(c[2]), "+f"(c[3])
                 : "r"(a[0]), "r"(a[1]), "r"(a[2]), "r"(a[3]), "r"(b[0]), "r"(b[1]));
}

// ---------------------------------------------------------------------------
// Kernel A (merged): blocks 0..255  -> per-(b,t) centroid + base (k-split x4)
//                    blocks 256..271 -> W2 -> bf16 hi/lo image conversion
// Block = 1024 threads.
// ---------------------------------------------------------------------------
__global__ void __launch_bounds__(1024) prep_kernel(
    const float* __restrict__ sf, const float* __restrict__ trans,
    const float* __restrict__ W1, const float* __restrict__ b1,
    const float* __restrict__ W2)
{
    const int t = threadIdx.x;

    if (blockIdx.x >= BT_N) {
        // ---- W2 conversion: 16 blocks x 1024 threads = 16384 items ----
        int idx = (blockIdx.x - BT_N) * 1024 + t;
        int n  = idx & 127;            // fast -> coalesced W2 loads
        int kp = idx >> 7;             // 0..127
        int k0 = kp * 2;
        float w0 = W2[k0 * HID + n];
        float w1 = W2[(k0 + 1) * HID + n];
        unsigned hw, lw;
        split_pair(w0, w1, hw, lw);
        g_Bhi[n * 128 + kp] = hw;
        g_Blo[n * 128 + kp] = lw;
        return;
    }

    __shared__ float sfs[DIM];
    __shared__ float part[1024];
    __shared__ float red0[1024], red1[1024], red2[1024];

    const int bt = blockIdx.x;
    if (t < DIM) sfs[t] = sf[bt * DIM + t];

    // centroid: 512 rows
    float sx = 0.f, sy = 0.f, sz = 0.f;
    if (t < RPT) {
        const float* p = trans + ((size_t)bt * RPT + t) * 3;
        sx = p[0]; sy = p[1]; sz = p[2];
    }
    red0[t] = sx; red1[t] = sy; red2[t] = sz;
    __syncthreads();
    for (int s = 512; s > 0; s >>= 1) {
        if (t < s) { red0[t] += red0[t+s]; red1[t] += red1[t+s]; red2[t] += red2[t+s]; }
        __syncthreads();
    }
    if (t == 0) {
        g_centroid[bt*3+0] = red0[0] * (1.0f/RPT);
        g_centroid[bt*3+1] = red1[0] * (1.0f/RPT);
        g_centroid[bt*3+2] = red2[0] * (1.0f/RPT);
    }

    // base: thread (c = t>>8, j = t&255) sums k in [64c, 64c+64)
    {
        const int c = t >> 8, j = t & 255;
        const float* wp = W1 + (size_t)(c * 64) * DIM + j;
        const float* sp = sfs + c * 64;
        float acc = 0.f;
        #pragma unroll 8
        for (int k = 0; k < 64; k++) acc += sp[k] * wp[k * DIM];
        part[t] = acc;
    }
    __syncthreads();
    if (t < DIM) {
        g_base[bt * DIM + t] = b1[t] + part[t] + part[256 + t] + part[512 + t] + part[768 + t];
    }
}

// ---------------------------------------------------------------------------
// Kernel B: fused head, GEMM2 via mma.sync bf16x3. Grid (4,256), 256 thr, 1 CTA/SM.
// ---------------------------------------------------------------------------
__global__ void __launch_bounds__(NTHR, 1) head_kernel(
    const float* __restrict__ quat, const float* __restrict__ trans,
    const float* __restrict__ W1, const float* __restrict__ b2,
    const float* __restrict__ Wt, const float* __restrict__ btp,
    const float* __restrict__ Wr, const float* __restrict__ brp,
    float* __restrict__ out)
{
    extern __shared__ char smp[];
    unsigned* smw = (unsigned*)smp;
    uint32_t sb = smem_u32(smp);

    float* misc   = (float*)smp + MISC_W;
    float* base_s = misc + MF_BASE;
    float* w1b    = misc + MF_W1B;
    float* quat_s = misc + MF_QUAT;
    float* lrp_s  = misc + MF_LRP;
    float* b2_s   = misc + MF_B2;
    float* wt_s   = misc + MF_WT;
    float* wr_s   = misc + MF_WR;
    float* btbr   = misc + MF_BTBR;
    float* stage  = misc + MF_STG;
    float* h2s    = (float*)smp;              // overlays A region after GEMM

    const int t    = threadIdx.x;
    const int lane = t & 31;
    const int wid  = t >> 5;
    const int bt   = blockIdx.y;
    const int r0   = blockIdx.x * MROWS;

    // ---- prefetch B k-half 0 via cp.async (drained after phase 1) ----
    #pragma unroll
    for (int i = t; i < 2048; i += NTHR) {
        int n = i >> 4, s = i & 15;
        uint32_t dh = sb + (uint32_t)(B_HI_W + n * B_STRIDE_W + s * 4) * 4u;
        uint32_t dl = sb + (uint32_t)(B_LO_W + n * B_STRIDE_W + s * 4) * 4u;
        cp_async16(dh, ((const uint4*)g_Bhi) + n * 32 + s);
        cp_async16(dl, ((const uint4*)g_Blo) + n * 32 + s);
    }
    asm volatile("cp.async.commit_group;" ::: "memory");

    // ---- cooperative loads ----
    base_s[t] = g_base[bt * DIM + t];
    for (int i = t; i < 3 * DIM; i += NTHR) w1b[i] = W1[DIM * DIM + i];
    for (int i = t; i < MROWS * 4; i += NTHR)
        quat_s[i] = quat[((size_t)bt * RPT + r0) * 4 + i];
    if (t < HID) b2_s[t] = b2[t];
    for (int i = t; i < HID * 3; i += NTHR) { wt_s[i] = Wt[i]; wr_s[i] = Wr[i]; }
    if (t < 3) { btbr[t] = btp[t]; btbr[4 + t] = brp[t]; }
    __syncthreads();

    // ---- local_rel_pos (conjugate rotation), 128 rows ----
    if (t < MROWS) {
        const float* tp = trans + ((size_t)bt * RPT + r0 + t) * 3;
        float vx = tp[0] - g_centroid[bt*3+0];
        float vy = tp[1] - g_centroid[bt*3+1];
        float vz = tp[2] - g_centroid[bt*3+2];
        float qw = quat_s[t*4+0], qx = quat_s[t*4+1], qy = quat_s[t*4+2], qz = quat_s[t*4+3];
        float o0, o1, o2;
        quat_rotate(qw, -qx, -qy, -qz, vx, vy, vz, o0, o1, o2);
        lrp_s[t*3+0] = o0; lrp_s[t*3+1] = o1; lrp_s[t*3+2] = o2;
    }
    __syncthreads();

    // ---- phase 1: h1 = gelu(base + lrp @ W1b) -> bf16 hi/lo into A images ----
    {
        int kp = t & 127, rh = t >> 7;
        int k0 = kp * 2;
        float b0 = base_s[k0], b1v = base_s[k0+1];
        float wa0 = w1b[k0],   wb0 = w1b[256+k0],   wc0 = w1b[512+k0];
        float wa1 = w1b[k0+1], wb1 = w1b[256+k0+1], wc1 = w1b[512+k0+1];
        #pragma unroll 4
        for (int r = 0; r < 64; r++) {
            int row = rh * 64 + r;
            float l0 = lrp_s[row*3+0], l1 = lrp_s[row*3+1], l2 = lrp_s[row*3+2];
            float v0 = gelu_tanh(b0  + l0*wa0 + l1*wb0 + l2*wc0);
            float v1 = gelu_tanh(b1v + l0*wa1 + l1*wb1 + l2*wc1);
            unsigned hw, lw;
            split_pair(v0, v1, hw, lw);
            int w = row * A_STRIDE_W + kp;
            smw[A_HI_W + w] = hw;
            smw[A_LO_W + w] = lw;
        }
    }

    // ---- GEMM2: C[128x128] = h1 @ W2, bf16x3 via mma.sync ----
    const int wm = wid >> 2;          // 0..1 (m half)
    const int wn = wid & 3;           // 0..3 (n quarter)

    float acc[4][4][4];
    #pragma unroll
    for (int i = 0; i < 4; i++)
        #pragma unroll
        for (int j = 0; j < 4; j++)
            #pragma unroll
            for (int k = 0; k < 4; k++) acc[i][j][k] = 0.f;

    // A ldmatrix lane addresses (bytes)
    uint32_t aAddrHi = sb + ((uint32_t)(wm*64 + (lane & 15)) * A_STRIDE_W
                             + ((lane >> 4) << 2)) * 4u;
    uint32_t aAddrLo = aAddrHi + A_LO_W * 4u;
    // B ldmatrix x4 lane addresses: serves two n-tiles per load
    const int bg = lane >> 3, bl8 = lane & 7;
    uint32_t bAddrHi = sb + (uint32_t)(B_HI_W
                             + (uint32_t)(wn*32 + ((bg & 2) << 2) + bl8) * B_STRIDE_W
                             + ((bg & 1) << 2)) * 4u;
    uint32_t bAddrLo = bAddrHi + (uint32_t)(B_LO_W - B_HI_W) * 4u;

    #pragma unroll 1
    for (int h = 0; h < 2; h++) {
        if (h) {
            __syncthreads();          // all h=0 MMAs done before B overwrite
            #pragma unroll
            for (int i = t; i < 2048; i += NTHR) {
                int n = i >> 4, s = i & 15;
                uint32_t dh = sb + (uint32_t)(B_HI_W + n * B_STRIDE_W + s * 4) * 4u;
                uint32_t dl = sb + (uint32_t)(B_LO_W + n * B_STRIDE_W + s * 4) * 4u;
                cp_async16(dh, ((const uint4*)g_Bhi) + n * 32 + 16 + s);
                cp_async16(dl, ((const uint4*)g_Blo) + n * 32 + 16 + s);
            }
            asm volatile("cp.async.commit_group;" ::: "memory");
        }
        asm volatile("cp.async.wait_group 0;" ::: "memory");
        __syncthreads();              // (h=0: also covers phase-1 A writes)

        uint32_t aK = (uint32_t)h * 256u;   // 64 words
        #pragma unroll 2
        for (int ks = 0; ks < 8; ks++) {
            unsigned ah[4][4], al[4][4], bh4[2][4], bl4[2][4];
            #pragma unroll
            for (int mt = 0; mt < 4; mt++) {
                uint32_t off = (uint32_t)mt * (16 * A_STRIDE_W * 4) + aK + (uint32_t)ks * 32u;
                ldsm_x4(ah[mt], aAddrHi + off);
                ldsm_x4(al[mt], aAddrLo + off);
            }
            #pragma unroll
            for (int np = 0; np < 2; np++) {
                uint32_t off = (uint32_t)np * (16 * B_STRIDE_W * 4) + (uint32_t)ks * 32u;
                ldsm_x4(bh4[np], bAddrHi + off);
                ldsm_x4(bl4[np], bAddrLo + off);
            }
            #pragma unroll
            for (int mt = 0; mt < 4; mt++)
                #pragma unroll
                for (int nt = 0; nt < 4; nt++) {
                    const unsigned* bh = &bh4[nt >> 1][(nt & 1) * 2];
                    const unsigned* bl = &bl4[nt >> 1][(nt & 1) * 2];
                    mma16816(acc[mt][nt], ah[mt], bh);
                    mma16816(acc[mt][nt], ah[mt], bl);
                    mma16816(acc[mt][nt], al[mt], bh);
                }
        }
    }
    __syncthreads();                   // all A reads done before h2 overlay

    // ---- epilogue: bias + gelu -> h2s (stride 132 words, overlays A) ----
    {
        const int q = lane & 3, g = lane >> 2;
        #pragma unroll
        for (int mt = 0; mt < 4; mt++) {
            int row = wm*64 + mt*16 + g;
            #pragma unroll
            for (int nt = 0; nt < 4; nt++) {
                int col = wn*32 + nt*8 + 2*q;
                float bA = b2_s[col], bB = b2_s[col+1];
                float2 v0; v0.x = gelu_tanh(acc[mt][nt][0] + bA);
                           v0.y = gelu_tanh(acc[mt][nt][1] + bB);
                float2 v1; v1.x = gelu_tanh(acc[mt][nt][2] + bA);
                           v1.y = gelu_tanh(acc[mt][nt][3] + bB);
                *(float2*)&h2s[row * A_STRIDE_W + col]       = v0;
                *(float2*)&h2s[(row+8) * A_STRIDE_W + col]   = v1;
            }
        }
    }
    __syncthreads();

    // ---- phase 3: heads, 2 threads/row, shfl reduce ----
    {
        const int row = t >> 1, sub = t & 1;
        const float* hrow = h2s + row * A_STRIDE_W;
        float s0=0.f,s1=0.f,s2=0.f,s3=0.f,s4=0.f,s5=0.f;
        #pragma unroll 8
        for (int j = 0; j < 64; j++) {
            int k = 2 * j + sub;
            float hv = hrow[k];
            s0 += hv * wt_s[k*3+0]; s1 += hv * wt_s[k*3+1]; s2 += hv * wt_s[k*3+2];
            s3 += hv * wr_s[k*3+0]; s4 += hv * wr_s[k*3+1]; s5 += hv * wr_s[k*3+2];
        }
        s0 += __shfl_xor_sync(0xffffffff, s0, 1);
        s1 += __shfl_xor_sync(0xffffffff, s1, 1);
        s2 += __shfl_xor_sync(0xffffffff, s2, 1);
        s3 += __shfl_xor_sync(0xffffffff, s3, 1);
        s4 += __shfl_xor_sync(0xffffffff, s4, 1);
        s5 += __shfl_xor_sync(0xffffffff, s5, 1);
        if (sub == 0) {
            float tv0 = s0 + btbr[0], tv1 = s1 + btbr[1], tv2 = s2 + btbr[2];
            float rv0 = (s3 + btbr[4]) * 0.1f;
            float rv1 = (s4 + btbr[5]) * 0.1f;
            float rv2 = (s5 + btbr[6]) * 0.1f;
            float qw = quat_s[row*4+0], qx = quat_s[row*4+1];
            float qy = quat_s[row*4+2], qz = quat_s[row*4+3];
            float wx, wy, wz;
            quat_rotate(qw, qx, qy, qz, tv0, tv1, tv2, wx, wy, wz);
            float qvw = 0.5f * (-qx*rv0 - qy*rv1 - qz*rv2);
            float qvx = 0.5f * ( qw*rv0 + qy*rv2 - qz*rv1);
            float qvy = 0.5f * ( qw*rv1 - qx*rv2 + qz*rv0);
            float qvz = 0.5f * ( qw*rv2 + qx*rv1 - qy*rv0);
            float* st = stage + row * 7;
            st[0]=qvw; st[1]=qvx; st[2]=qvy; st[3]=qvz; st[4]=wx; st[5]=wy; st[6]=wz;
        }
    }
    __syncthreads();

    // coalesced store: 896 contiguous floats per CTA
    {
        float* obase = out + ((size_t)bt * RPT + r0) * 7;
        #pragma unroll
        for (int i = 0; i < 3; i++) obase[t + i * NTHR] = stage[t + i * NTHR];
        if (t < 128) obase[t + 768] = stage[t + 768];
    }
}

// ---------------------------------------------------------------------------
extern "C" void kernel_launch(void* const* d_in, const int* in_sizes, int n_in,
                              void* d_out, int out_size) {
    const float* sf    = (const float*)d_in[0];
    const float* quat  = (const float*)d_in[1];
    const float* trans = (const float*)d_in[2];
    const float* W1    = (const float*)d_in[3];
    const float* b1    = (const float*)d_in[4];
    const float* W2    = (const float*)d_in[5];
    const float* b2    = (const float*)d_in[6];
    const float* Wt    = (const float*)d_in[7];
    const float* btp   = (const float*)d_in[8];
    const float* Wr    = (const float*)d_in[9];
    const float* brp   = (const float*)d_in[10];
    float* out = (float*)d_out;

    cudaFuncSetAttribute(head_kernel, cudaFuncAttributeMaxDynamicSharedMemorySize,
                         SMEM_BYTES);

    prep_kernel<<<BT_N + 16, 1024>>>(sf, trans, W1, b1, W2);

    dim3 grid(RPT / MROWS, BT_N);    // (4, 256)
    head_kernel<<<grid, NTHR, SMEM_BYTES>>>(quat, trans, W1, b2, Wt, btp, Wr, brp, out);
}

// round 12
// speedup vs baseline: 2.6291x; 1.0955x over previous
#include <cuda_runtime.h>
#include <cuda_bf16.h>
#include <cstdint>

// Problem constants
#define BT_N   256      // B*T
#define RPT    512
#define DIM    256      // D (= K of GEMM2)
#define HID    128      // D/2 (= N of GEMM2)
#define MROWS  128      // rows per CTA (= M of GEMM2 tile)
#define HTHR   512      // head kernel threads (16 warps)

// Scratch (device globals -- no allocation allowed)
__device__ float g_centroid[BT_N * 3];
__device__ float g_base[BT_N * DIM];
// W2^T bf16 hi/lo images: [n=128][kword=128] (k-major, 2 bf16 per word)
__device__ __align__(16) unsigned g_Bhi[16384];
__device__ __align__(16) unsigned g_Blo[16384];

// ---- smem word-layout (word = 4 bytes) ----
#define A_STRIDE_W 132
#define A_HI_W     0
#define A_LO_W     16896                  // 128*132
#define B_STRIDE_W 68                     // 68 % 32 == 4 -> conflict-free ldmatrix
#define B_HI_W     33792
#define B_LO_W     42496                  // 33792 + 128*68
#define MISC_W     51200                  // 42496 + 8704
// misc float offsets (within misc region)
#define MF_BASE 0
#define MF_W1B  256
#define MF_QUAT 1024
#define MF_LRP  1536
#define MF_B2   1920
#define MF_WT   2048
#define MF_WR   2432
#define MF_BTBR 2816
#define MF_STG  2824
#define MISC_FLOATS 3720
#define SMEM_BYTES ((MISC_W + MISC_FLOATS) * 4)     // 219680

// ---------------- helpers ----------------
__device__ __forceinline__ uint32_t smem_u32(const void* p) {
    uint32_t a;
    asm("{ .reg .u64 t; cvta.to.shared.u64 t, %1; cvt.u32.u64 %0, t; }" : "=r"(a) : "l"(p));
    return a;
}
__device__ __forceinline__ void cp_async16(uint32_t dst, const void* src) {
    asm volatile("cp.async.cg.shared.global [%0], [%1], 16;" :: "r"(dst), "l"(src) : "memory");
}
__device__ __forceinline__ float fast_tanh(float x) {
    float y; asm("tanh.approx.f32 %0, %1;" : "=f"(y) : "f"(x)); return y;
}
__device__ __forceinline__ float gelu_tanh(float v) {
    float u = 0.7978845608028654f * (v + 0.044715f * v * v * v);
    return 0.5f * v * (1.0f + fast_tanh(u));
}
// hi = truncate-to-bf16 (top 16 bits), lo = rn-bf16 of remainder; packs 2 values.
__device__ __forceinline__ void split_pair(float v0, float v1,
                                           unsigned& hi_word, unsigned& lo_word) {
    unsigned u0 = __float_as_uint(v0), u1 = __float_as_uint(v1);
    hi_word = __byte_perm(u0, u1, 0x7632);           // {u0.hi16, u1.hi16}
    float l0 = v0 - __uint_as_float(u0 & 0xFFFF0000u);
    float l1 = v1 - __uint_as_float(u1 & 0xFFFF0000u);
    asm("cvt.rn.satfinite.bf16x2.f32 %0, %1, %2;" : "=r"(lo_word) : "f"(l1), "f"(l0));
}
__device__ __forceinline__ void quat_rotate(float w, float x, float y, float z,
                                            float vx, float vy, float vz,
                                            float& ox, float& oy, float& oz) {
    float n = sqrtf(w * w + x * x + y * y + z * z);
    float inv = 1.0f / (n + 1e-8f);
    w *= inv; x *= inv; y *= inv; z *= inv;
    float xx = x * x, yy = y * y, zz = z * z;
    float xy = x * y, xz = x * z, yz = y * z;
    float wx = w * x, wy = w * y, wz = w * z;
    ox = (1.f - 2.f * (yy + zz)) * vx + 2.f * (xy - wz) * vy + 2.f * (xz + wy) * vz;
    oy = 2.f * (xy + wz) * vx + (1.f - 2.f * (xx + zz)) * vy + 2.f * (yz - wx) * vz;
    oz = 2.f * (xz - wy) * vx + 2.f * (yz + wx) * vy + (1.f - 2.f * (xx + yy)) * vz;
}
__device__ __forceinline__ void ldsm_x4(unsigned* r, uint32_t addr) {
    asm volatile("ldmatrix.sync.aligned.m8n8.x4.shared.b16 {%0,%1,%2,%3}, [%4];"
                 : "=r"(r[0]), "=r"(r[1]), "=r"(r[2]), "=r"(r[3]) : "r"(addr));
}
__device__ __forceinline__ void mma16816(float* c, const unsigned* a, const unsigned* b) {
    asm volatile("mma.sync.aligned.m16n8k16.row.col.f32.bf16.bf16.f32 "
                 "{%0,%1,%2,%3}, {%4,%5,%6,%7}, {%8,%9}, {%0,%1,%2,%3};"
                 : "+f"(c[0]), "+f"(c[1]), "+f"(c[2]), "+f"(c[3])
                 : "r"(a[0]), "r"(a[1]), "r"(a[2]), "r"(a[3]), "r"(b[0]), "r"(b[1]));
}

// ---------------------------------------------------------------------------
// Kernel A (merged): blocks 0..255  -> per-(b,t) centroid + base (k-split x4)
//                    blocks 256..271 -> W2 -> bf16 hi/lo image conversion
// Block = 1024 threads.
// ---------------------------------------------------------------------------
__global__ void __launch_bounds__(1024) prep_kernel(
    const float* __restrict__ sf, const float* __restrict__ trans,
    const float* __restrict__ W1, const float* __restrict__ b1,
    const float* __restrict__ W2)
{
    const int t = threadIdx.x;

    if (blockIdx.x >= BT_N) {
        // ---- W2 conversion: 16 blocks x 1024 threads = 16384 items ----
        int idx = (blockIdx.x - BT_N) * 1024 + t;
        int n  = idx & 127;            // fast -> coalesced W2 loads
        int kp = idx >> 7;             // 0..127
        int k0 = kp * 2;
        float w0 = W2[k0 * HID + n];
        float w1 = W2[(k0 + 1) * HID + n];
        unsigned hw, lw;
        split_pair(w0, w1, hw, lw);
        g_Bhi[n * 128 + kp] = hw;
        g_Blo[n * 128 + kp] = lw;
        return;
    }

    __shared__ float sfs[DIM];
    __shared__ float part[1024];
    __shared__ float red0[1024], red1[1024], red2[1024];

    const int bt = blockIdx.x;
    if (t < DIM) sfs[t] = sf[bt * DIM + t];

    // centroid: 512 rows
    float sx = 0.f, sy = 0.f, sz = 0.f;
    if (t < RPT) {
        const float* p = trans + ((size_t)bt * RPT + t) * 3;
        sx = p[0]; sy = p[1]; sz = p[2];
    }
    red0[t] = sx; red1[t] = sy; red2[t] = sz;
    __syncthreads();
    for (int s = 512; s > 0; s >>= 1) {
        if (t < s) { red0[t] += red0[t+s]; red1[t] += red1[t+s]; red2[t] += red2[t+s]; }
        __syncthreads();
    }
    if (t == 0) {
        g_centroid[bt*3+0] = red0[0] * (1.0f/RPT);
        g_centroid[bt*3+1] = red1[0] * (1.0f/RPT);
        g_centroid[bt*3+2] = red2[0] * (1.0f/RPT);
    }

    // base: thread (c = t>>8, j = t&255) sums k in [64c, 64c+64)
    {
        const int c = t >> 8, j = t & 255;
        const float* wp = W1 + (size_t)(c * 64) * DIM + j;
        const float* sp = sfs + c * 64;
        float acc = 0.f;
        #pragma unroll 8
        for (int k = 0; k < 64; k++) acc += sp[k] * wp[k * DIM];
        part[t] = acc;
    }
    __syncthreads();
    if (t < DIM) {
        g_base[bt * DIM + t] = b1[t] + part[t] + part[256 + t] + part[512 + t] + part[768 + t];
    }
}

// ---------------------------------------------------------------------------
// Kernel B: fused head, GEMM2 via mma.sync bf16x3.
// Grid (4,256), 512 threads (16 warps, 4m x 4n warp grid), 1 CTA/SM.
// ---------------------------------------------------------------------------
__global__ void __launch_bounds__(HTHR, 1) head_kernel(
    const float* __restrict__ quat, const float* __restrict__ trans,
    const float* __restrict__ W1, const float* __restrict__ b2,
    const float* __restrict__ Wt, const float* __restrict__ btp,
    const float* __restrict__ Wr, const float* __restrict__ brp,
    float* __restrict__ out)
{
    extern __shared__ char smp[];
    unsigned* smw = (unsigned*)smp;
    uint32_t sb = smem_u32(smp);

    float* misc   = (float*)smp + MISC_W;
    float* base_s = misc + MF_BASE;
    float* w1b    = misc + MF_W1B;
    float* quat_s = misc + MF_QUAT;
    float* lrp_s  = misc + MF_LRP;
    float* b2_s   = misc + MF_B2;
    float* wt_s   = misc + MF_WT;
    float* wr_s   = misc + MF_WR;
    float* btbr   = misc + MF_BTBR;
    float* stage  = misc + MF_STG;
    float* h2s    = (float*)smp;              // overlays A region after GEMM

    const int t    = threadIdx.x;
    const int lane = t & 31;
    const int wid  = t >> 5;
    const int bt   = blockIdx.y;
    const int r0   = blockIdx.x * MROWS;

    // ---- prefetch B k-half 0 via cp.async (drained after phase 1) ----
    #pragma unroll
    for (int i = t; i < 2048; i += HTHR) {
        int n = i >> 4, s = i & 15;
        uint32_t dh = sb + (uint32_t)(B_HI_W + n * B_STRIDE_W + s * 4) * 4u;
        uint32_t dl = sb + (uint32_t)(B_LO_W + n * B_STRIDE_W + s * 4) * 4u;
        cp_async16(dh, ((const uint4*)g_Bhi) + n * 32 + s);
        cp_async16(dl, ((const uint4*)g_Blo) + n * 32 + s);
    }
    asm volatile("cp.async.commit_group;" ::: "memory");

    // ---- cooperative loads ----
    if (t < DIM) base_s[t] = g_base[bt * DIM + t];
    for (int i = t; i < 3 * DIM; i += HTHR) w1b[i] = W1[DIM * DIM + i];
    quat_s[t] = quat[((size_t)bt * RPT + r0) * 4 + t];      // 128 rows * 4 = 512
    if (t < HID) b2_s[t] = b2[t];
    if (t < HID * 3) { wt_s[t] = Wt[t]; wr_s[t] = Wr[t]; }
    if (t < 3) { btbr[t] = btp[t]; btbr[4 + t] = brp[t]; }
    __syncthreads();

    // ---- local_rel_pos (conjugate rotation), 128 rows ----
    if (t < MROWS) {
        const float* tp = trans + ((size_t)bt * RPT + r0 + t) * 3;
        float vx = tp[0] - g_centroid[bt*3+0];
        float vy = tp[1] - g_centroid[bt*3+1];
        float vz = tp[2] - g_centroid[bt*3+2];
        float qw = quat_s[t*4+0], qx = quat_s[t*4+1], qy = quat_s[t*4+2], qz = quat_s[t*4+3];
        float o0, o1, o2;
        quat_rotate(qw, -qx, -qy, -qz, vx, vy, vz, o0, o1, o2);
        lrp_s[t*3+0] = o0; lrp_s[t*3+1] = o1; lrp_s[t*3+2] = o2;
    }
    __syncthreads();

    // ---- phase 1: h1 = gelu(base + lrp @ W1b) -> bf16 hi/lo into A images ----
    {
        int kp = t & 127, rh = t >> 7;          // rh in 0..3, 32 rows each
        int k0 = kp * 2;
        float b0 = base_s[k0], b1v = base_s[k0+1];
        float wa0 = w1b[k0],   wb0 = w1b[256+k0],   wc0 = w1b[512+k0];
        float wa1 = w1b[k0+1], wb1 = w1b[256+k0+1], wc1 = w1b[512+k0+1];
        #pragma unroll 4
        for (int r = 0; r < 32; r++) {
            int row = rh * 32 + r;
            float l0 = lrp_s[row*3+0], l1 = lrp_s[row*3+1], l2 = lrp_s[row*3+2];
            float v0 = gelu_tanh(b0  + l0*wa0 + l1*wb0 + l2*wc0);
            float v1 = gelu_tanh(b1v + l0*wa1 + l1*wb1 + l2*wc1);
            unsigned hw, lw;
            split_pair(v0, v1, hw, lw);
            int w = row * A_STRIDE_W + kp;
            smw[A_HI_W + w] = hw;
            smw[A_LO_W + w] = lw;
        }
    }

    // ---- GEMM2: C[128x128] = h1 @ W2, bf16x3 via mma.sync ----
    const int wm = wid >> 2;          // 0..3 (m quarter, 32 rows)
    const int wn = wid & 3;           // 0..3 (n quarter, 32 cols)

    float acc[2][4][4];
    #pragma unroll
    for (int i = 0; i < 2; i++)
        #pragma unroll
        for (int j = 0; j < 4; j++)
            #pragma unroll
            for (int k = 0; k < 4; k++) acc[i][j][k] = 0.f;

    // A ldmatrix lane addresses (bytes)
    uint32_t aAddrHi = sb + ((uint32_t)(wm*32 + (lane & 15)) * A_STRIDE_W
                             + ((lane >> 4) << 2)) * 4u;
    uint32_t aAddrLo = aAddrHi + A_LO_W * 4u;
    // B ldmatrix x4 lane addresses: serves two n-tiles per load
    const int bg = lane >> 3, bl8 = lane & 7;
    uint32_t bAddrHi = sb + (uint32_t)(B_HI_W
                             + (uint32_t)(wn*32 + ((bg & 2) << 2) + bl8) * B_STRIDE_W
                             + ((bg & 1) << 2)) * 4u;
    uint32_t bAddrLo = bAddrHi + (uint32_t)(B_LO_W - B_HI_W) * 4u;

    #pragma unroll 1
    for (int h = 0; h < 2; h++) {
        if (h) {
            __syncthreads();          // all h=0 MMAs done before B overwrite
            #pragma unroll
            for (int i = t; i < 2048; i += HTHR) {
                int n = i >> 4, s = i & 15;
                uint32_t dh = sb + (uint32_t)(B_HI_W + n * B_STRIDE_W + s * 4) * 4u;
                uint32_t dl = sb + (uint32_t)(B_LO_W + n * B_STRIDE_W + s * 4) * 4u;
                cp_async16(dh, ((const uint4*)g_Bhi) + n * 32 + 16 + s);
                cp_async16(dl, ((const uint4*)g_Blo) + n * 32 + 16 + s);
            }
            asm volatile("cp.async.commit_group;" ::: "memory");
        }
        asm volatile("cp.async.wait_group 0;" ::: "memory");
        __syncthreads();              // (h=0: also covers phase-1 A writes)

        uint32_t aK = (uint32_t)h * 256u;   // 64 words
        #pragma unroll 2
        for (int ks = 0; ks < 8; ks++) {
            unsigned ah[2][4], al[2][4], bh4[2][4], bl4[2][4];
            #pragma unroll
            for (int mt = 0; mt < 2; mt++) {
                uint32_t off = (uint32_t)mt * (16 * A_STRIDE_W * 4) + aK + (uint32_t)ks * 32u;
                ldsm_x4(ah[mt], aAddrHi + off);
                ldsm_x4(al[mt], aAddrLo + off);
            }
            #pragma unroll
            for (int np = 0; np < 2; np++) {
                uint32_t off = (uint32_t)np * (16 * B_STRIDE_W * 4) + (uint32_t)ks * 32u;
                ldsm_x4(bh4[np], bAddrHi + off);
                ldsm_x4(bl4[np], bAddrLo + off);
            }
            #pragma unroll
            for (int mt = 0; mt < 2; mt++)
                #pragma unroll
                for (int nt = 0; nt < 4; nt++) {
                    const unsigned* bh = &bh4[nt >> 1][(nt & 1) * 2];
                    const unsigned* bl = &bl4[nt >> 1][(nt & 1) * 2];
                    mma16816(acc[mt][nt], ah[mt], bh);
                    mma16816(acc[mt][nt], ah[mt], bl);
                    mma16816(acc[mt][nt], al[mt], bh);
                }
        }
    }
    __syncthreads();                   // all A reads done before h2 overlay

    // ---- epilogue: bias + gelu -> h2s (stride 132 words, overlays A) ----
    {
        const int q = lane & 3, g = lane >> 2;
        #pragma unroll
        for (int mt = 0; mt < 2; mt++) {
            int row = wm*32 + mt*16 + g;
            #pragma unroll
            for (int nt = 0; nt < 4; nt++) {
                int col = wn*32 + nt*8 + 2*q;
                float bA = b2_s[col], bB = b2_s[col+1];
                float2 v0; v0.x = gelu_tanh(acc[mt][nt][0] + bA);
                           v0.y = gelu_tanh(acc[mt][nt][1] + bB);
                float2 v1; v1.x = gelu_tanh(acc[mt][nt][2] + bA);
                           v1.y = gelu_tanh(acc[mt][nt][3] + bB);
                *(float2*)&h2s[row * A_STRIDE_W + col]       = v0;
                *(float2*)&h2s[(row+8) * A_STRIDE_W + col]   = v1;
            }
        }
    }
    __syncthreads();

    // ---- phase 3: heads, 4 threads/row (interleaved k), shfl reduce ----
    {
        const int row = t >> 2, sub = t & 3;
        const float* hrow = h2s + row * A_STRIDE_W;
        float s0=0.f,s1=0.f,s2=0.f,s3=0.f,s4=0.f,s5=0.f;
        #pragma unroll 8
        for (int j = 0; j < 32; j++) {
            int k = 4 * j + sub;
            float hv = hrow[k];
            s0 += hv * wt_s[k*3+0]; s1 += hv * wt_s[k*3+1]; s2 += hv * wt_s[k*3+2];
            s3 += hv * wr_s[k*3+0]; s4 += hv * wr_s[k*3+1]; s5 += hv * wr_s[k*3+2];
        }
        #pragma unroll
        for (int m = 1; m <= 2; m <<= 1) {
            s0 += __shfl_xor_sync(0xffffffff, s0, m);
            s1 += __shfl_xor_sync(0xffffffff, s1, m);
            s2 += __shfl_xor_sync(0xffffffff, s2, m);
            s3 += __shfl_xor_sync(0xffffffff, s3, m);
            s4 += __shfl_xor_sync(0xffffffff, s4, m);
            s5 += __shfl_xor_sync(0xffffffff, s5, m);
        }
        if (sub == 0) {
            float tv0 = s0 + btbr[0], tv1 = s1 + btbr[1], tv2 = s2 + btbr[2];
            float rv0 = (s3 + btbr[4]) * 0.1f;
            float rv1 = (s4 + btbr[5]) * 0.1f;
            float rv2 = (s5 + btbr[6]) * 0.1f;
            float qw = quat_s[row*4+0], qx = quat_s[row*4+1];
            float qy = quat_s[row*4+2], qz = quat_s[row*4+3];
            float wx, wy, wz;
            quat_rotate(qw, qx, qy, qz, tv0, tv1, tv2, wx, wy, wz);
            float qvw = 0.5f * (-qx*rv0 - qy*rv1 - qz*rv2);
            float qvx = 0.5f * ( qw*rv0 + qy*rv2 - qz*rv1);
            float qvy = 0.5f * ( qw*rv1 - qx*rv2 + qz*rv0);
            float qvz = 0.5f * ( qw*rv2 + qx*rv1 - qy*rv0);
            float* st = stage + row * 7;
            st[0]=qvw; st[1]=qvx; st[2]=qvy; st[3]=qvz; st[4]=wx; st[5]=wy; st[6]=wz;
        }
    }
    __syncthreads();

    // coalesced store: 896 contiguous floats per CTA
    {
        float* obase = out + ((size_t)bt * RPT + r0) * 7;
        obase[t] = stage[t];
        if (t < 896 - HTHR) obase[t + HTHR] = stage[t + HTHR];
    }
}

// ---------------------------------------------------------------------------
extern "C" void kernel_launch(void* const* d_in, const int* in_sizes, int n_in,
                              void* d_out, int out_size) {
    const float* sf    = (const float*)d_in[0];
    const float* quat  = (const float*)d_in[1];
    const float* trans = (const float*)d_in[2];
    const float* W1    = (const float*)d_in[3];
    const float* b1    = (const float*)d_in[4];
    const float* W2    = (const float*)d_in[5];
    const float* b2    = (const float*)d_in[6];
    const float* Wt    = (const float*)d_in[7];
    const float* btp   = (const float*)d_in[8];
    const float* Wr    = (const float*)d_in[9];
    const float* brp   = (const float*)d_in[10];
    float* out = (float*)d_out;

    cudaFuncSetAttribute(head_kernel, cudaFuncAttributeMaxDynamicSharedMemorySize,
                         SMEM_BYTES);

    prep_kernel<<<BT_N + 16, 1024>>>(sf, trans, W1, b1, W2);

    dim3 grid(RPT / MROWS, BT_N);    // (4, 256)
    head_kernel<<<grid, HTHR, SMEM_BYTES>>>(quat, trans, W1, b2, Wt, btp, Wr, brp, out);
}

// round 13
// speedup vs baseline: 2.6630x; 1.0129x over previous
#include <cuda_runtime.h>
#include <cuda_bf16.h>
#include <cstdint>

// Problem constants
#define BT_N   256      // B*T
#define RPT    512
#define DIM    256      // D (= K of GEMM2)
#define HID    128      // D/2 (= N of GEMM2)
#define MROWS  64       // rows per CTA (= M of GEMM2 tile)
#define HTHR   256      // head kernel threads (8 warps)

// Scratch (device globals -- no allocation allowed)
__device__ float g_centroid[BT_N * 3];
__device__ float g_base[BT_N * DIM];
// W2^T bf16 hi/lo images: [n=128][kword=128] (k-major, 2 bf16 per word)
__device__ __align__(16) unsigned g_Bhi[16384];
__device__ __align__(16) unsigned g_Blo[16384];

// ---- smem word-layout (word = 4 bytes) ----
#define A_STRIDE_W 132                    // 132 % 32 == 4 -> conflict-free ldmatrix
#define A_HI_W     0
#define A_LO_W     8448                   // 64*132
#define B_STRIDE_W 36                     // 36 % 32 == 4 -> conflict-free ldmatrix
#define B_HI_W     16896
#define B_LO_W     21504                  // 16896 + 128*36
#define MISC_W     26112                  // 21504 + 4608
// misc float offsets (within misc region)
#define MF_BASE 0
#define MF_QUAT 256
#define MF_LRP  512
#define MF_B2   704
#define MF_WT   832
#define MF_WR   1216
#define MF_BTBR 1600
#define MISC_FLOATS 1608
#define SMEM_BYTES ((MISC_W + MISC_FLOATS) * 4)     // 110880 -> 2 CTAs/SM

// ---------------- helpers ----------------
__device__ __forceinline__ uint32_t smem_u32(const void* p) {
    uint32_t a;
    asm("{ .reg .u64 t; cvta.to.shared.u64 t, %1; cvt.u32.u64 %0, t; }" : "=r"(a) : "l"(p));
    return a;
}
__device__ __forceinline__ void cp_async16(uint32_t dst, const void* src) {
    asm volatile("cp.async.cg.shared.global [%0], [%1], 16;" :: "r"(dst), "l"(src) : "memory");
}
__device__ __forceinline__ float fast_tanh(float x) {
    float y; asm("tanh.approx.f32 %0, %1;" : "=f"(y) : "f"(x)); return y;
}
__device__ __forceinline__ float gelu_tanh(float v) {
    float u = 0.7978845608028654f * (v + 0.044715f * v * v * v);
    return 0.5f * v * (1.0f + fast_tanh(u));
}
// hi = truncate-to-bf16 (top 16 bits), lo = rn-bf16 of remainder; packs 2 values.
__device__ __forceinline__ void split_pair(float v0, float v1,
                                           unsigned& hi_word, unsigned& lo_word) {
    unsigned u0 = __float_as_uint(v0), u1 = __float_as_uint(v1);
    hi_word = __byte_perm(u0, u1, 0x7632);           // {u0.hi16, u1.hi16}
    float l0 = v0 - __uint_as_float(u0 & 0xFFFF0000u);
    float l1 = v1 - __uint_as_float(u1 & 0xFFFF0000u);
    asm("cvt.rn.satfinite.bf16x2.f32 %0, %1, %2;" : "=r"(lo_word) : "f"(l1), "f"(l0));
}
__device__ __forceinline__ void quat_rotate(float w, float x, float y, float z,
                                            float vx, float vy, float vz,
                                            float& ox, float& oy, float& oz) {
    float n = sqrtf(w * w + x * x + y * y + z * z);
    float inv = 1.0f / (n + 1e-8f);
    w *= inv; x *= inv; y *= inv; z *= inv;
    float xx = x * x, yy = y * y, zz = z * z;
    float xy = x * y, xz = x * z, yz = y * z;
    float wx = w * x, wy = w * y, wz = w * z;
    ox = (1.f - 2.f * (yy + zz)) * vx + 2.f * (xy - wz) * vy + 2.f * (xz + wy) * vz;
    oy = 2.f * (xy + wz) * vx + (1.f - 2.f * (xx + zz)) * vy + 2.f * (yz - wx) * vz;
    oz = 2.f * (xz - wy) * vx + 2.f * (yz + wx) * vy + (1.f - 2.f * (xx + yy)) * vz;
}
__device__ __forceinline__ void ldsm_x4(unsigned* r, uint32_t addr) {
    asm volatile("ldmatrix.sync.aligned.m8n8.x4.shared.b16 {%0,%1,%2,%3}, [%4];"
                 : "=r"(r[0]), "=r"(r[1]), "=r"(r[2]), "=r"(r[3]) : "r"(addr));
}
__device__ __forceinline__ void mma16816(float* c, const unsigned* a, const unsigned* b) {
    asm volatile("mma.sync.aligned.m16n8k16.row.col.f32.bf16.bf16.f32 "
                 "{%0,%1,%2,%3}, {%4,%5,%6,%7}, {%8,%9}, {%0,%1,%2,%3};"
                 : "+f"(c[0]), "+f"(c[1]), "+f"(c[2]), "+f"(c[3])
                 : "r"(a[0]), "r"(a[1]), "r"(a[2]), "r"(a[3]), "r"(b[0]), "r"(b[1]));
}

// ---------------------------------------------------------------------------
// Kernel A (merged): blocks 0..255  -> per-(b,t) centroid + base (k-split x4)
//                    blocks 256..271 -> W2 -> bf16 hi/lo image conversion
// Block = 1024 threads.
// ---------------------------------------------------------------------------
__global__ void __launch_bounds__(1024) prep_kernel(
    const float* __restrict__ sf, const float* __restrict__ trans,
    const float* __restrict__ W1, const float* __restrict__ b1,
    const float* __restrict__ W2)
{
    const int t = threadIdx.x;

    if (blockIdx.x >= BT_N) {
        // ---- W2 conversion: 16 blocks x 1024 threads = 16384 items ----
        int idx = (blockIdx.x - BT_N) * 1024 + t;
        int n  = idx & 127;            // fast -> coalesced W2 loads
        int kp = idx >> 7;             // 0..127
        int k0 = kp * 2;
        float w0 = W2[k0 * HID + n];
        float w1 = W2[(k0 + 1) * HID + n];
        unsigned hw, lw;
        split_pair(w0, w1, hw, lw);
        g_Bhi[n * 128 + kp] = hw;
        g_Blo[n * 128 + kp] = lw;
        return;
    }

    __shared__ float sfs[DIM];
    __shared__ float part[1024];
    __shared__ float red0[1024], red1[1024], red2[1024];

    const int bt = blockIdx.x;
    if (t < DIM) sfs[t] = sf[bt * DIM + t];

    // centroid: 512 rows
    float sx = 0.f, sy = 0.f, sz = 0.f;
    if (t < RPT) {
        const float* p = trans + ((size_t)bt * RPT + t) * 3;
        sx = p[0]; sy = p[1]; sz = p[2];
    }
    red0[t] = sx; red1[t] = sy; red2[t] = sz;
    __syncthreads();
    for (int s = 512; s > 0; s >>= 1) {
        if (t < s) { red0[t] += red0[t+s]; red1[t] += red1[t+s]; red2[t] += red2[t+s]; }
        __syncthreads();
    }
    if (t == 0) {
        g_centroid[bt*3+0] = red0[0] * (1.0f/RPT);
        g_centroid[bt*3+1] = red1[0] * (1.0f/RPT);
        g_centroid[bt*3+2] = red2[0] * (1.0f/RPT);
    }

    // base: thread (c = t>>8, j = t&255) sums k in [64c, 64c+64)
    {
        const int c = t >> 8, j = t & 255;
        const float* wp = W1 + (size_t)(c * 64) * DIM + j;
        const float* sp = sfs + c * 64;
        float acc = 0.f;
        #pragma unroll 8
        for (int k = 0; k < 64; k++) acc += sp[k] * wp[k * DIM];
        part[t] = acc;
    }
    __syncthreads();
    if (t < DIM) {
        g_base[bt * DIM + t] = b1[t] + part[t] + part[256 + t] + part[512 + t] + part[768 + t];
    }
}

// ---------------------------------------------------------------------------
// Kernel B: fused head, GEMM2 via mma.sync bf16x3.
// Grid (8,256), 256 threads (8 warps, 2m x 4n), 2 CTAs/SM.
// B (W2 images) streamed in K-quarters through a single 36.8KB buffer.
// ---------------------------------------------------------------------------
__global__ void __launch_bounds__(HTHR, 2) head_kernel(
    const float* __restrict__ quat, const float* __restrict__ trans,
    const float* __restrict__ W1, const float* __restrict__ b2,
    const float* __restrict__ Wt, const float* __restrict__ btp,
    const float* __restrict__ Wr, const float* __restrict__ brp,
    float* __restrict__ out)
{
    extern __shared__ char smp[];
    unsigned* smw = (unsigned*)smp;
    uint32_t sb = smem_u32(smp);

    float* misc   = (float*)smp + MISC_W;
    float* base_s = misc + MF_BASE;
    float* quat_s = misc + MF_QUAT;
    float* lrp_s  = misc + MF_LRP;
    float* b2_s   = misc + MF_B2;
    float* wt_s   = misc + MF_WT;
    float* wr_s   = misc + MF_WR;
    float* btbr   = misc + MF_BTBR;
    float* h2s    = (float*)smp;                     // overlays A after GEMM
    float* stage  = (float*)smp + B_HI_W;            // overlays B after GEMM

    const int t    = threadIdx.x;
    const int lane = t & 31;
    const int wid  = t >> 5;
    const int bt   = blockIdx.y;
    const int r0   = blockIdx.x * MROWS;

    // ---- prefetch B k-quarter 0 via cp.async (drained after phase 1) ----
    #pragma unroll
    for (int i = t; i < 2048; i += HTHR) {
        int img = i >> 10;                // 0 = hi, 1 = lo
        int j = i & 1023, n = j >> 3, s = j & 7;
        uint32_t dst = sb + (uint32_t)((img ? B_LO_W : B_HI_W) + n * B_STRIDE_W + s * 4) * 4u;
        const uint4* src = ((const uint4*)(img ? g_Blo : g_Bhi)) + n * 32 + s;
        cp_async16(dst, src);
    }
    asm volatile("cp.async.commit_group;" ::: "memory");

    // ---- cooperative loads ----
    base_s[t] = g_base[bt * DIM + t];
    quat_s[t] = quat[((size_t)bt * RPT + r0) * 4 + t];      // 64 rows * 4 = 256
    if (t < HID) b2_s[t] = b2[t];
    for (int i = t; i < HID * 3; i += HTHR) { wt_s[i] = Wt[i]; wr_s[i] = Wr[i]; }
    if (t < 3) { btbr[t] = btp[t]; btbr[4 + t] = brp[t]; }
    __syncthreads();

    // ---- local_rel_pos (conjugate rotation), 64 rows ----
    if (t < MROWS) {
        const float* tp = trans + ((size_t)bt * RPT + r0 + t) * 3;
        float vx = tp[0] - g_centroid[bt*3+0];
        float vy = tp[1] - g_centroid[bt*3+1];
        float vz = tp[2] - g_centroid[bt*3+2];
        float qw = quat_s[t*4+0], qx = quat_s[t*4+1], qy = quat_s[t*4+2], qz = quat_s[t*4+3];
        float o0, o1, o2;
        quat_rotate(qw, -qx, -qy, -qz, vx, vy, vz, o0, o1, o2);
        lrp_s[t*3+0] = o0; lrp_s[t*3+1] = o1; lrp_s[t*3+2] = o2;
    }
    __syncthreads();

    // ---- phase 1: h1 = gelu(base + lrp @ W1b) -> bf16 hi/lo into A images ----
    {
        int kp = t & 127, rh = t >> 7;          // rh in 0..1, 32 rows each
        int k0 = kp * 2;
        const float* w1r = W1 + DIM * DIM;      // rows 256..258 (L2-resident)
        float b0 = base_s[k0], b1v = base_s[k0+1];
        float wa0 = __ldg(w1r + k0),       wb0 = __ldg(w1r + 256 + k0),
              wc0 = __ldg(w1r + 512 + k0);
        float wa1 = __ldg(w1r + k0 + 1),   wb1 = __ldg(w1r + 256 + k0 + 1),
              wc1 = __ldg(w1r + 512 + k0 + 1);
        #pragma unroll 4
        for (int r = 0; r < 32; r++) {
            int row = rh * 32 + r;
            float l0 = lrp_s[row*3+0], l1 = lrp_s[row*3+1], l2 = lrp_s[row*3+2];
            float v0 = gelu_tanh(b0  + l0*wa0 + l1*wb0 + l2*wc0);
            float v1 = gelu_tanh(b1v + l0*wa1 + l1*wb1 + l2*wc1);
            unsigned hw, lw;
            split_pair(v0, v1, hw, lw);
            int w = row * A_STRIDE_W + kp;
            smw[A_HI_W + w] = hw;
            smw[A_LO_W + w] = lw;
        }
    }

    // ---- GEMM2: C[64x128] = h1 @ W2, bf16x3 via mma.sync, K-quarter streaming ----
    const int wm = wid >> 2;          // 0..1 (m half, 32 rows)
    const int wn = wid & 3;           // 0..3 (n quarter, 32 cols)

    float acc[2][4][4];
    #pragma unroll
    for (int i = 0; i < 2; i++)
        #pragma unroll
        for (int j = 0; j < 4; j++)
            #pragma unroll
            for (int k = 0; k < 4; k++) acc[i][j][k] = 0.f;

    // A ldmatrix lane addresses (bytes)
    uint32_t aAddrHi = sb + ((uint32_t)(wm*32 + (lane & 15)) * A_STRIDE_W
                             + ((lane >> 4) << 2)) * 4u;
    uint32_t aAddrLo = aAddrHi + A_LO_W * 4u;
    // B ldmatrix x4 lane addresses: serves two n-tiles per load
    const int bg = lane >> 3, bl8 = lane & 7;
    uint32_t bAddrHi = sb + (uint32_t)(B_HI_W
                             + (uint32_t)(wn*32 + ((bg & 2) << 2) + bl8) * B_STRIDE_W
                             + ((bg & 1) << 2)) * 4u;
    uint32_t bAddrLo = bAddrHi + (uint32_t)(B_LO_W - B_HI_W) * 4u;

    #pragma unroll 1
    for (int q = 0; q < 4; q++) {
        if (q) {
            __syncthreads();          // quarter q-1 MMAs done before B overwrite
            #pragma unroll
            for (int i = t; i < 2048; i += HTHR) {
                int img = i >> 10;
                int j = i & 1023, n = j >> 3, s = j & 7;
                uint32_t dst = sb + (uint32_t)((img ? B_LO_W : B_HI_W)
                                               + n * B_STRIDE_W + s * 4) * 4u;
                const uint4* src = ((const uint4*)(img ? g_Blo : g_Bhi))
                                   + n * 32 + q * 8 + s;
                cp_async16(dst, src);
            }
            asm volatile("cp.async.commit_group;" ::: "memory");
        }
        asm volatile("cp.async.wait_group 0;" ::: "memory");
        __syncthreads();              // (q=0: also covers phase-1 A writes)

        #pragma unroll
        for (int ks = 0; ks < 4; ks++) {
            unsigned ah[2][4], al[2][4], bh4[2][4], bl4[2][4];
            uint32_t aCol = (uint32_t)(q * 4 + ks) * 32u;     // bytes
            #pragma unroll
            for (int mt = 0; mt < 2; mt++) {
                uint32_t off = (uint32_t)mt * (16 * A_STRIDE_W * 4) + aCol;
                ldsm_x4(ah[mt], aAddrHi + off);
                ldsm_x4(al[mt], aAddrLo + off);
            }
            #pragma unroll
            for (int np = 0; np < 2; np++) {
                uint32_t off = (uint32_t)np * (16 * B_STRIDE_W * 4) + (uint32_t)ks * 32u;
                ldsm_x4(bh4[np], bAddrHi + off);
                ldsm_x4(bl4[np], bAddrLo + off);
            }
            #pragma unroll
            for (int mt = 0; mt < 2; mt++)
                #pragma unroll
                for (int nt = 0; nt < 4; nt++) {
                    const unsigned* bh = &bh4[nt >> 1][(nt & 1) * 2];
                    const unsigned* bl = &bl4[nt >> 1][(nt & 1) * 2];
                    mma16816(acc[mt][nt], ah[mt], bh);
                    mma16816(acc[mt][nt], ah[mt], bl);
                    mma16816(acc[mt][nt], al[mt], bh);
                }
        }
    }
    __syncthreads();                   // all A reads done before h2 overlay

    // ---- epilogue: bias + gelu -> h2s (stride 132 words, overlays A) ----
    {
        const int qq = lane & 3, g = lane >> 2;
        #pragma unroll
        for (int mt = 0; mt < 2; mt++) {
            int row = wm*32 + mt*16 + g;
            #pragma unroll
            for (int nt = 0; nt < 4; nt++) {
                int col = wn*32 + nt*8 + 2*qq;
                float bA = b2_s[col], bB = b2_s[col+1];
                float2 v0; v0.x = gelu_tanh(acc[mt][nt][0] + bA);
                           v0.y = gelu_tanh(acc[mt][nt][1] + bB);
                float2 v1; v1.x = gelu_tanh(acc[mt][nt][2] + bA);
                           v1.y = gelu_tanh(acc[mt][nt][3] + bB);
                *(float2*)&h2s[row * A_STRIDE_W + col]       = v0;
                *(float2*)&h2s[(row+8) * A_STRIDE_W + col]   = v1;
            }
        }
    }
    __syncthreads();

    // ---- phase 3: heads, 4 threads/row (interleaved k), shfl reduce ----
    {
        const int row = t >> 2, sub = t & 3;
        const float* hrow = h2s + row * A_STRIDE_W;
        float s0=0.f,s1=0.f,s2=0.f,s3=0.f,s4=0.f,s5=0.f;
        #pragma unroll 8
        for (int j = 0; j < 32; j++) {
            int k = 4 * j + sub;
            float hv = hrow[k];
            s0 += hv * wt_s[k*3+0]; s1 += hv * wt_s[k*3+1]; s2 += hv * wt_s[k*3+2];
            s3 += hv * wr_s[k*3+0]; s4 += hv * wr_s[k*3+1]; s5 += hv * wr_s[k*3+2];
        }
        #pragma unroll
        for (int m = 1; m <= 2; m <<= 1) {
            s0 += __shfl_xor_sync(0xffffffff, s0, m);
            s1 += __shfl_xor_sync(0xffffffff, s1, m);
            s2 += __shfl_xor_sync(0xffffffff, s2, m);
            s3 += __shfl_xor_sync(0xffffffff, s3, m);
            s4 += __shfl_xor_sync(0xffffffff, s4, m);
            s5 += __shfl_xor_sync(0xffffffff, s5, m);
        }
        if (sub == 0) {
            float tv0 = s0 + btbr[0], tv1 = s1 + btbr[1], tv2 = s2 + btbr[2];
            float rv0 = (s3 + btbr[4]) * 0.1f;
            float rv1 = (s4 + btbr[5]) * 0.1f;
            float rv2 = (s5 + btbr[6]) * 0.1f;
            float qw = quat_s[row*4+0], qx = quat_s[row*4+1];
            float qy = quat_s[row*4+2], qz = quat_s[row*4+3];
            float wx, wy, wz;
            quat_rotate(qw, qx, qy, qz, tv0, tv1, tv2, wx, wy, wz);
            float qvw = 0.5f * (-qx*rv0 - qy*rv1 - qz*rv2);
            float qvx = 0.5f * ( qw*rv0 + qy*rv2 - qz*rv1);
            float qvy = 0.5f * ( qw*rv1 - qx*rv2 + qz*rv0);
            float qvz = 0.5f * ( qw*rv2 + qx*rv1 - qy*rv0);
            float* st = stage + row * 7;
            st[0]=qvw; st[1]=qvx; st[2]=qvy; st[3]=qvz; st[4]=wx; st[5]=wy; st[6]=wz;
        }
    }
    __syncthreads();

    // coalesced store: 448 contiguous floats per CTA
    {
        float* obase = out + ((size_t)bt * RPT + r0) * 7;
        obase[t] = stage[t];
        if (t < 448 - HTHR) obase[t + HTHR] = stage[t + HTHR];
    }
}

// ---------------------------------------------------------------------------
extern "C" void kernel_launch(void* const* d_in, const int* in_sizes, int n_in,
                              void* d_out, int out_size) {
    const float* sf    = (const float*)d_in[0];
    const float* quat  = (const float*)d_in[1];
    const float* trans = (const float*)d_in[2];
    const float* W1    = (const float*)d_in[3];
    const float* b1    = (const float*)d_in[4];
    const float* W2    = (const float*)d_in[5];
    const float* b2    = (const float*)d_in[6];
    const float* Wt    = (const float*)d_in[7];
    const float* btp   = (const float*)d_in[8];
    const float* Wr    = (const float*)d_in[9];
    const float* brp   = (const float*)d_in[10];
    float* out = (float*)d_out;

    cudaFuncSetAttribute(head_kernel, cudaFuncAttributeMaxDynamicSharedMemorySize,
                         SMEM_BYTES);

    prep_kernel<<<BT_N + 16, 1024>>>(sf, trans, W1, b1, W2);

    dim3 grid(RPT / MROWS, BT_N);    // (8, 256)
    head_kernel<<<grid, HTHR, SMEM_BYTES>>>(quat, trans, W1, b2, Wt, btp, Wr, brp, out);
}

// round 15
// speedup vs baseline: 2.9205x; 1.0967x over previous
#include <cuda_runtime.h>
#include <cuda_bf16.h>
#include <cstdint>

// Problem constants
#define BT_N   256      // B*T
#define RPT    512
#define DIM    256      // D (= K of GEMM2)
#define HID    128      // D/2 (= N of GEMM2)
#define MROWS  64       // rows per CTA (= M of GEMM2 tile)
#define HTHR   256      // head kernel threads (8 warps)

// Scratch (device globals -- no allocation allowed)
__device__ float g_centroid[BT_N * 3];
__device__ float g_base[BT_N * DIM];
// W2^T bf16 hi/lo images: [n=128][kword=128] (k-major, 2 bf16 per word)
__device__ __align__(16) unsigned g_Bhi[16384];
__device__ __align__(16) unsigned g_Blo[16384];
// [Wt|Wr|0|0] bf16 hi/lo images for phase-3 MMA: [n=8][kpair=64]
__device__ __align__(16) unsigned g_B3hi[512];
__device__ __align__(16) unsigned g_B3lo[512];

// ---- smem word-layout (word = 4 bytes) ----
#define A_STRIDE_W 132                    // 132 % 32 == 4 -> conflict-free ldmatrix
#define A_HI_W     0
#define A_LO_W     8448                   // 64*132
#define B_STRIDE_W 36                     // 36 % 32 == 4 -> conflict-free ldmatrix
#define B_HI_W     16896
#define B_LO_W     21504                  // 16896 + 128*36
#define MISC_W     26112                  // 21504 + 4608
// misc float offsets (within misc region)
#define MF_BASE 0
#define MF_QUAT 256
#define MF_LRP  512
#define MF_B2   704
#define MF_WT   832
#define MF_WR   1216
#define MF_BTBR 1600
#define MISC_FLOATS 1608
#define SMEM_BYTES ((MISC_W + MISC_FLOATS) * 4)     // 110880 -> 2 CTAs/SM

// ---------------- helpers ----------------
__device__ __forceinline__ uint32_t smem_u32(const void* p) {
    uint32_t a;
    asm("{ .reg .u64 t; cvta.to.shared.u64 t, %1; cvt.u32.u64 %0, t; }" : "=r"(a) : "l"(p));
    return a;
}
__device__ __forceinline__ void cp_async16(uint32_t dst, const void* src) {
    asm volatile("cp.async.cg.shared.global [%0], [%1], 16;" :: "r"(dst), "l"(src) : "memory");
}
__device__ __forceinline__ float fast_tanh(float x) {
    float y; asm("tanh.approx.f32 %0, %1;" : "=f"(y) : "f"(x)); return y;
}
__device__ __forceinline__ float gelu_tanh(float v) {
    float u = 0.7978845608028654f * (v + 0.044715f * v * v * v);
    return 0.5f * v * (1.0f + fast_tanh(u));
}
// hi = truncate-to-bf16 (top 16 bits) of two floats, packed
__device__ __forceinline__ unsigned hi_pack(float v0, float v1) {
    return __byte_perm(__float_as_uint(v0), __float_as_uint(v1), 0x7632);
}
// lo = rn-bf16 of remainders, packed (elem0 low half)
__device__ __forceinline__ unsigned lo_pack(float v0, float v1) {
    float l0 = v0 - __uint_as_float(__float_as_uint(v0) & 0xFFFF0000u);
    float l1 = v1 - __uint_as_float(__float_as_uint(v1) & 0xFFFF0000u);
    unsigned w;
    asm("cvt.rn.satfinite.bf16x2.f32 %0, %1, %2;" : "=r"(w) : "f"(l1), "f"(l0));
    return w;
}
__device__ __forceinline__ void split_pair(float v0, float v1,
                                           unsigned& hi_word, unsigned& lo_word) {
    hi_word = hi_pack(v0, v1);
    lo_word = lo_pack(v0, v1);
}
__device__ __forceinline__ void quat_rotate(float w, float x, float y, float z,
                                            float vx, float vy, float vz,
                                            float& ox, float& oy, float& oz) {
    float n = sqrtf(w * w + x * x + y * y + z * z);
    float inv = 1.0f / (n + 1e-8f);
    w *= inv; x *= inv; y *= inv; z *= inv;
    float xx = x * x, yy = y * y, zz = z * z;
    float xy = x * y, xz = x * z, yz = y * z;
    float wx = w * x, wy = w * y, wz = w * z;
    ox = (1.f - 2.f * (yy + zz)) * vx + 2.f * (xy - wz) * vy + 2.f * (xz + wy) * vz;
    oy = 2.f * (xy + wz) * vx + (1.f - 2.f * (xx + zz)) * vy + 2.f * (yz - wx) * vz;
    oz = 2.f * (xz - wy) * vx + 2.f * (yz + wx) * vy + (1.f - 2.f * (xx + yy)) * vz;
}
__device__ __forceinline__ void ldsm_x4(unsigned* r, uint32_t addr) {
    asm volatile("ldmatrix.sync.aligned.m8n8.x4.shared.b16 {%0,%1,%2,%3}, [%4];"
                 : "=r"(r[0]), "=r"(r[1]), "=r"(r[2]), "=r"(r[3]) : "r"(addr));
}
__device__ __forceinline__ void mma16816(float* c, const unsigned* a, const unsigned* b) {
    asm volatile("mma.sync.aligned.m16n8k16.row.col.f32.bf16.bf16.f32 "
                 "{%0,%1,%2,%3}, {%4,%5,%6,%7}, {%8,%9}, {%0,%1,%2,%3};"
                 : "+f"(c[0]), "+f"(c[1]), "+f"(c[2]), "+f"(c[3])
                 : "r"(a[0]), "r"(a[1]), "r"(a[2]), "r"(a[3]), "r"(b[0]), "r"(b[1]));
}

// ---------------------------------------------------------------------------
// Kernel A (merged): blocks 0..255   -> per-(b,t) centroid + base (k-split x4)
//                    blocks 256..271 -> W2 -> bf16 hi/lo image conversion
//                    block  272      -> [Wt|Wr] -> B3 hi/lo fragments image
// Block = 1024 threads.
// ---------------------------------------------------------------------------
__global__ void __launch_bounds__(1024) prep_kernel(
    const float* __restrict__ sf, const float* __restrict__ trans,
    const float* __restrict__ W1, const float* __restrict__ b1,
    const float* __restrict__ W2,
    const float* __restrict__ Wt, const float* __restrict__ Wr)
{
    const int t = threadIdx.x;

    if (blockIdx.x >= BT_N) {
        int cb = blockIdx.x - BT_N;
        if (cb < 16) {
            // ---- W2 conversion: 16 blocks x 1024 threads = 16384 items ----
            int idx = cb * 1024 + t;
            int n  = idx & 127;            // fast -> coalesced W2 loads
            int kp = idx >> 7;             // 0..127
            int k0 = kp * 2;
            float w0 = W2[k0 * HID + n];
            float w1 = W2[(k0 + 1) * HID + n];
            unsigned hw, lw;
            split_pair(w0, w1, hw, lw);
            g_Bhi[n * 128 + kp] = hw;
            g_Blo[n * 128 + kp] = lw;
        } else if (t < 512) {
            // ---- B3 = [Wt|Wr|0|0] conversion: 8 n x 64 kpairs ----
            int n  = t >> 6;               // 0..7
            int kp = t & 63;               // 0..63
            int k0 = kp * 2;
            float w0 = 0.f, w1 = 0.f;
            if (n < 3)      { w0 = Wt[k0 * 3 + n];       w1 = Wt[(k0 + 1) * 3 + n]; }
            else if (n < 6) { w0 = Wr[k0 * 3 + (n - 3)]; w1 = Wr[(k0 + 1) * 3 + (n - 3)]; }
            unsigned hw, lw;
            split_pair(w0, w1, hw, lw);
            g_B3hi[n * 64 + kp] = hw;
            g_B3lo[n * 64 + kp] = lw;
        }
        return;
    }

    __shared__ float sfs[DIM];
    __shared__ float part[1024];
    __shared__ float red0[1024], red1[1024], red2[1024];

    const int bt = blockIdx.x;
    if (t < DIM) sfs[t] = sf[bt * DIM + t];

    // centroid: 512 rows
    float sx = 0.f, sy = 0.f, sz = 0.f;
    if (t < RPT) {
        const float* p = trans + ((size_t)bt * RPT + t) * 3;
        sx = p[0]; sy = p[1]; sz = p[2];
    }
    red0[t] = sx; red1[t] = sy; red2[t] = sz;
    __syncthreads();
    for (int s = 512; s > 0; s >>= 1) {
        if (t < s) { red0[t] += red0[t+s]; red1[t] += red1[t+s]; red2[t] += red2[t+s]; }
        __syncthreads();
    }
    if (t == 0) {
        g_centroid[bt*3+0] = red0[0] * (1.0f/RPT);
        g_centroid[bt*3+1] = red1[0] * (1.0f/RPT);
        g_centroid[bt*3+2] = red2[0] * (1.0f/RPT);
    }

    // base: thread (c = t>>8, j = t&255) sums k in [64c, 64c+64)
    {
        const int c = t >> 8, j = t & 255;
        const float* wp = W1 + (size_t)(c * 64) * DIM + j;
        const float* sp = sfs + c * 64;
        float acc = 0.f;
        #pragma unroll 8
        for (int k = 0; k < 64; k++) acc += sp[k] * wp[k * DIM];
        part[t] = acc;
    }
    __syncthreads();
    if (t < DIM) {
        g_base[bt * DIM + t] = b1[t] + part[t] + part[256 + t] + part[512 + t] + part[768 + t];
    }
}

// ---------------------------------------------------------------------------
// Kernel B: fused head, GEMM2 via mma.sync bf16x3, phase-3 heads via MMA too.
// Grid (8,256), 256 threads (8 warps, 2m x 4n), 2 CTAs/SM.
// ---------------------------------------------------------------------------
__global__ void __launch_bounds__(HTHR, 2) head_kernel(
    const float* __restrict__ quat, const float* __restrict__ trans,
    const float* __restrict__ W1, const float* __restrict__ b2,
    const float* __restrict__ btp, const float* __restrict__ brp,
    float* __restrict__ out)
{
    extern __shared__ char smp[];
    unsigned* smw = (unsigned*)smp;
    uint32_t sb = smem_u32(smp);

    float* misc   = (float*)smp + MISC_W;
    float* base_s = misc + MF_BASE;
    float* quat_s = misc + MF_QUAT;
    float* lrp_s  = misc + MF_LRP;
    float* b2_s   = misc + MF_B2;
    float* btbr   = misc + MF_BTBR;
    float* part3  = (float*)smp + B_HI_W;            // overlays B after GEMM: [4][64][9]
    float* stage  = (float*)smp;                     // overlays A after GEMM

    const int t    = threadIdx.x;
    const int lane = t & 31;
    const int wid  = t >> 5;
    const int bt   = blockIdx.y;
    const int r0   = blockIdx.x * MROWS;

    // ---- prefetch B k-quarter 0 via cp.async (drained after phase 1) ----
    #pragma unroll
    for (int i = t; i < 2048; i += HTHR) {
        int img = i >> 10;                // 0 = hi, 1 = lo
        int j = i & 1023, n = j >> 3, s = j & 7;
        uint32_t dst = sb + (uint32_t)((img ? B_LO_W : B_HI_W) + n * B_STRIDE_W + s * 4) * 4u;
        const uint4* src = ((const uint4*)(img ? g_Blo : g_Bhi)) + n * 32 + s;
        cp_async16(dst, src);
    }
    asm volatile("cp.async.commit_group;" ::: "memory");

    // ---- cooperative loads ----
    base_s[t] = g_base[bt * DIM + t];
    quat_s[t] = quat[((size_t)bt * RPT + r0) * 4 + t];      // 64 rows * 4 = 256
    if (t < HID) b2_s[t] = b2[t];
    if (t < 3) { btbr[t] = btp[t]; btbr[4 + t] = brp[t]; }
    __syncthreads();

    // ---- local_rel_pos (conjugate rotation), 64 rows ----
    if (t < MROWS) {
        const float* tp = trans + ((size_t)bt * RPT + r0 + t) * 3;
        float vx = tp[0] - g_centroid[bt*3+0];
        float vy = tp[1] - g_centroid[bt*3+1];
        float vz = tp[2] - g_centroid[bt*3+2];
        float qw = quat_s[t*4+0], qx = quat_s[t*4+1], qy = quat_s[t*4+2], qz = quat_s[t*4+3];
        float o0, o1, o2;
        quat_rotate(qw, -qx, -qy, -qz, vx, vy, vz, o0, o1, o2);
        lrp_s[t*3+0] = o0; lrp_s[t*3+1] = o1; lrp_s[t*3+2] = o2;
    }
    __syncthreads();

    // ---- phase 1: h1 = gelu(base + lrp @ W1b) -> bf16 hi/lo into A images ----
    {
        int kp = t & 127, rh = t >> 7;          // rh in 0..1, 32 rows each
        int k0 = kp * 2;
        const float* w1r = W1 + DIM * DIM;      // rows 256..258 (L2-resident)
        float b0 = base_s[k0], b1v = base_s[k0+1];
        float wa0 = __ldg(w1r + k0),       wb0 = __ldg(w1r + 256 + k0),
              wc0 = __ldg(w1r + 512 + k0);
        float wa1 = __ldg(w1r + k0 + 1),   wb1 = __ldg(w1r + 256 + k0 + 1),
              wc1 = __ldg(w1r + 512 + k0 + 1);
        #pragma unroll 4
        for (int r = 0; r < 32; r++) {
            int row = rh * 32 + r;
            float l0 = lrp_s[row*3+0], l1 = lrp_s[row*3+1], l2 = lrp_s[row*3+2];
            float v0 = gelu_tanh(b0  + l0*wa0 + l1*wb0 + l2*wc0);
            float v1 = gelu_tanh(b1v + l0*wa1 + l1*wb1 + l2*wc1);
            unsigned hw, lw;
            split_pair(v0, v1, hw, lw);
            int w = row * A_STRIDE_W + kp;
            smw[A_HI_W + w] = hw;
            smw[A_LO_W + w] = lw;
        }
    }

    // ---- GEMM2: C[64x128] = h1 @ W2, bf16x3 via mma.sync, K-quarter streaming ----
    const int wm = wid >> 2;          // 0..1 (m half, 32 rows)
    const int wn = wid & 3;           // 0..3 (n quarter, 32 cols)

    float acc[2][4][4];
    #pragma unroll
    for (int i = 0; i < 2; i++)
        #pragma unroll
        for (int j = 0; j < 4; j++)
            #pragma unroll
            for (int k = 0; k < 4; k++) acc[i][j][k] = 0.f;

    // A ldmatrix lane addresses (bytes)
    uint32_t aAddrHi = sb + ((uint32_t)(wm*32 + (lane & 15)) * A_STRIDE_W
                             + ((lane >> 4) << 2)) * 4u;
    uint32_t aAddrLo = aAddrHi + A_LO_W * 4u;
    // B ldmatrix x4 lane addresses: serves two n-tiles per load
    const int bg = lane >> 3, bl8 = lane & 7;
    uint32_t bAddrHi = sb + (uint32_t)(B_HI_W
                             + (uint32_t)(wn*32 + ((bg & 2) << 2) + bl8) * B_STRIDE_W
                             + ((bg & 1) << 2)) * 4u;
    uint32_t bAddrLo = bAddrHi + (uint32_t)(B_LO_W - B_HI_W) * 4u;

    #pragma unroll 1
    for (int q = 0; q < 4; q++) {
        if (q) {
            __syncthreads();          // quarter q-1 MMAs done before B overwrite
            #pragma unroll
            for (int i = t; i < 2048; i += HTHR) {
                int img = i >> 10;
                int j = i & 1023, n = j >> 3, s = j & 7;
                uint32_t dst = sb + (uint32_t)((img ? B_LO_W : B_HI_W)
                                               + n * B_STRIDE_W + s * 4) * 4u;
                const uint4* src = ((const uint4*)(img ? g_Blo : g_Bhi))
                                   + n * 32 + q * 8 + s;
                cp_async16(dst, src);
            }
            asm volatile("cp.async.commit_group;" ::: "memory");
        }
        asm volatile("cp.async.wait_group 0;" ::: "memory");
        __syncthreads();              // (q=0: also covers phase-1 A writes)

        #pragma unroll
        for (int ks = 0; ks < 4; ks++) {
            unsigned ah[2][4], al[2][4], bh4[2][4], bl4[2][4];
            uint32_t aCol = (uint32_t)(q * 4 + ks) * 32u;     // bytes
            #pragma unroll
            for (int mt = 0; mt < 2; mt++) {
                uint32_t off = (uint32_t)mt * (16 * A_STRIDE_W * 4) + aCol;
                ldsm_x4(ah[mt], aAddrHi + off);
                ldsm_x4(al[mt], aAddrLo + off);
            }
            #pragma unroll
            for (int np = 0; np < 2; np++) {
                uint32_t off = (uint32_t)np * (16 * B_STRIDE_W * 4) + (uint32_t)ks * 32u;
                ldsm_x4(bh4[np], bAddrHi + off);
                ldsm_x4(bl4[np], bAddrLo + off);
            }
            #pragma unroll
            for (int mt = 0; mt < 2; mt++)
                #pragma unroll
                for (int nt = 0; nt < 4; nt++) {
                    const unsigned* bh = &bh4[nt >> 1][(nt & 1) * 2];
                    const unsigned* bl = &bl4[nt >> 1][(nt & 1) * 2];
                    mma16816(acc[mt][nt], ah[mt], bh);
                    mma16816(acc[mt][nt], ah[mt], bl);
                    mma16816(acc[mt][nt], al[mt], bh);
                }
        }
    }

    // ---- epilogue: gelu in regs, then phase-3 heads via MMA (no h2 smem) ----
    const int q3 = lane & 3, g3 = lane >> 2;

    // gelu(acc + b2) in place
    #pragma unroll
    for (int mt = 0; mt < 2; mt++)
        #pragma unroll
        for (int nt = 0; nt < 4; nt++) {
            int col = wn*32 + nt*8 + 2*q3;
            float bA = b2_s[col], bB = b2_s[col+1];
            acc[mt][nt][0] = gelu_tanh(acc[mt][nt][0] + bA);
            acc[mt][nt][1] = gelu_tanh(acc[mt][nt][1] + bB);
            acc[mt][nt][2] = gelu_tanh(acc[mt][nt][2] + bA);
            acc[mt][nt][3] = gelu_tanh(acc[mt][nt][3] + bB);
        }

    // B3 fragments (constant per warp): [Wt|Wr|0|0] hi/lo, k-slice = h2 cols of this warp
    unsigned b3h[2][2], b3l[2][2];
    {
        int n3 = lane >> 2;                     // 0..7 (col of B3)
        #pragma unroll
        for (int kk = 0; kk < 2; kk++) {
            int base = n3 * 64 + ((wn*32 + kk*16) >> 1) + q3;
            b3h[kk][0] = g_B3hi[base];     b3h[kk][1] = g_B3hi[base + 4];
            b3l[kk][0] = g_B3lo[base];     b3l[kk][1] = g_B3lo[base + 4];
        }
    }

    // C3 partials: rows of this warp x 8 cols, k-summed over this warp's 32 h2-cols
    float c3[2][4];
    #pragma unroll
    for (int mt = 0; mt < 2; mt++) {
        c3[mt][0] = c3[mt][1] = c3[mt][2] = c3[mt][3] = 0.f;
        #pragma unroll
        for (int kk = 0; kk < 2; kk++) {
            unsigned aH[4], aL[4];
            const float* c0 = acc[mt][2*kk];        // k 2q,2q+1 block
            const float* c1 = acc[mt][2*kk + 1];    // k 2q+8,2q+9 block
            aH[0] = hi_pack(c0[0], c0[1]);  aH[1] = hi_pack(c0[2], c0[3]);
            aH[2] = hi_pack(c1[0], c1[1]);  aH[3] = hi_pack(c1[2], c1[3]);
            aL[0] = lo_pack(c0[0], c0[1]);  aL[1] = lo_pack(c0[2], c0[3]);
            aL[2] = lo_pack(c1[0], c1[1]);  aL[3] = lo_pack(c1[2], c1[3]);
            mma16816(c3[mt], aH, b3h[kk]);
            mma16816(c3[mt], aH, b3l[kk]);
            mma16816(c3[mt], aL, b3h[kk]);
        }
    }

    __syncthreads();                   // all mainloop smem reads done; B region reusable

    // write partials: part3[wn][row][9]
    #pragma unroll
    for (int mt = 0; mt < 2; mt++) {
        int row0 = wm*32 + mt*16 + g3;
        part3[(wn*64 + row0) * 9 + 2*q3]     = c3[mt][0];
        part3[(wn*64 + row0) * 9 + 2*q3 + 1] = c3[mt][1];
        part3[(wn*64 + row0 + 8) * 9 + 2*q3]     = c3[mt][2];
        part3[(wn*64 + row0 + 8) * 9 + 2*q3 + 1] = c3[mt][3];
    }
    __syncthreads();

    // ---- reduce partials + quaternion algebra (64 threads, 1 per row) ----
    if (t < MROWS) {
        float s[6];
        #pragma unroll
        for (int c = 0; c < 6; c++)
            s[c] = part3[t*9 + c] + part3[(64 + t)*9 + c]
                 + part3[(128 + t)*9 + c] + part3[(192 + t)*9 + c];

        float tv0 = s[0] + btbr[0], tv1 = s[1] + btbr[1], tv2 = s[2] + btbr[2];
        float rv0 = (s[3] + btbr[4]) * 0.1f;
        float rv1 = (s[4] + btbr[5]) * 0.1f;
        float rv2 = (s[5] + btbr[6]) * 0.1f;
        float qw = quat_s[t*4+0], qx = quat_s[t*4+1];
        float qy = quat_s[t*4+2], qz = quat_s[t*4+3];
        float wx, wy, wz;
        quat_rotate(qw, qx, qy, qz, tv0, tv1, tv2, wx, wy, wz);
        float qvw = 0.5f * (-qx*rv0 - qy*rv1 - qz*rv2);
        float qvx = 0.5f * ( qw*rv0 + qy*rv2 - qz*rv1);
        float qvy = 0.5f * ( qw*rv1 - qx*rv2 + qz*rv0);
        float qvz = 0.5f * ( qw*rv2 + qx*rv1 - qy*rv0);
        float* st = stage + t * 7;
        st[0]=qvw; st[1]=qvx; st[2]=qvy; st[3]=qvz; st[4]=wx; st[5]=wy; st[6]=wz;
    }
    __syncthreads();

    // coalesced store: 448 contiguous floats per CTA
    {
        float* obase = out + ((size_t)bt * RPT + r0) * 7;
        obase[t] = stage[t];
        if (t < 448 - HTHR) obase[t + HTHR] = stage[t + HTHR];
    }
}

// ---------------------------------------------------------------------------
extern "C" void kernel_launch(void* const* d_in, const int* in_sizes, int n_in,
                              void* d_out, int out_size) {
    const float* sf    = (const float*)d_in[0];
    const float* quat  = (const float*)d_in[1];
    const float* trans = (const float*)d_in[2];
    const float* W1    = (const float*)d_in[3];
    const float* b1    = (const float*)d_in[4];
    const float* W2    = (const float*)d_in[5];
    const float* b2    = (const float*)d_in[6];
    const float* Wt    = (const float*)d_in[7];
    const float* btp   = (const float*)d_in[8];
    const float* Wr    = (const float*)d_in[9];
    const float* brp   = (const float*)d_in[10];
    float* out = (float*)d_out;

    cudaFuncSetAttribute(head_kernel, cudaFuncAttributeMaxDynamicSharedMemorySize,
                         SMEM_BYTES);

    prep_kernel<<<BT_N + 17, 1024>>>(sf, trans, W1, b1, W2, Wt, Wr);

    dim3 grid(RPT / MROWS, BT_N);    // (8, 256)
    head_kernel<<<grid, HTHR, SMEM_BYTES>>>(quat, trans, W1, b2, btp, brp, out);
}

// round 17
// speedup vs baseline: 3.0356x; 1.0394x over previous
#include <cuda_runtime.h>
#include <cuda_bf16.h>
#include <cstdint>

// Problem constants
#define BT_N   256      // B*T
#define RPT    512
#define DIM    256      // D (= K of GEMM2)
#define HID    128      // D/2 (= N of GEMM2)
#define MROWS  64       // rows per CTA (= M of GEMM2 tile)
#define HTHR   256      // head kernel threads (8 warps)

typedef unsigned long long ull;

// Scratch (device globals -- no allocation allowed)
__device__ float g_centroid[BT_N * 3];
__device__ float g_base[BT_N * DIM];
// W2^T bf16 hi/lo images: [n=128][kword=128] (k-major, 2 bf16 per word)
__device__ __align__(16) unsigned g_Bhi[16384];
__device__ __align__(16) unsigned g_Blo[16384];
// [Wt|Wr|0|0] bf16 hi/lo images for phase-3 MMA: [n=8][kpair=64]
__device__ __align__(16) unsigned g_B3hi[512];
__device__ __align__(16) unsigned g_B3lo[512];

// ---- smem word-layout (word = 4 bytes) ----
#define A_STRIDE_W 132                    // 132 % 32 == 4 -> conflict-free ldmatrix
#define A_HI_W     0
#define A_LO_W     8448                   // 64*132
#define B_STRIDE_W 36                     // 36 % 32 == 4 -> conflict-free ldmatrix
#define B_HI_W     16896
#define B_LO_W     21504                  // 16896 + 128*36
#define MISC_W     26112                  // 21504 + 4608
// misc float offsets (within misc region)
#define MF_BASE 0
#define MF_W1B  256
#define MF_QUAT 1024
#define MF_LRP  1280
#define MF_B2   1472
#define MF_BTBR 1600
#define MISC_FLOATS 1608
#define SMEM_BYTES ((MISC_W + MISC_FLOATS) * 4)     // 110880 -> 2 CTAs/SM

// ---------------- helpers ----------------
__device__ __forceinline__ uint32_t smem_u32(const void* p) {
    uint32_t a;
    asm("{ .reg .u64 t; cvta.to.shared.u64 t, %1; cvt.u32.u64 %0, t; }" : "=r"(a) : "l"(p));
    return a;
}
__device__ __forceinline__ void cp_async16(uint32_t dst, const void* src) {
    asm volatile("cp.async.cg.shared.global [%0], [%1], 16;" :: "r"(dst), "l"(src) : "memory");
}
__device__ __forceinline__ float fast_tanh(float x) {
    float y; asm("tanh.approx.f32 %0, %1;" : "=f"(y) : "f"(x)); return y;
}
__device__ __forceinline__ float gelu_tanh(float v) {
    float u = 0.7978845608028654f * (v + 0.044715f * v * v * v);
    return 0.5f * v * (1.0f + fast_tanh(u));
}
// packed f32x2 helpers
__device__ __forceinline__ ull pk2(float lo, float hi) {
    ull r; asm("mov.b64 %0, {%1, %2};" : "=l"(r) : "f"(lo), "f"(hi)); return r;
}
__device__ __forceinline__ void upk2(ull v, float& lo, float& hi) {
    asm("mov.b64 {%0, %1}, %2;" : "=f"(lo), "=f"(hi) : "l"(v));
}
__device__ __forceinline__ ull fma2(ull a, ull b, ull c) {
    ull d; asm("fma.rn.f32x2 %0, %1, %2, %3;" : "=l"(d) : "l"(a), "l"(b), "l"(c)); return d;
}
// hi = truncate-to-bf16 (top 16 bits) of two floats, packed
__device__ __forceinline__ unsigned hi_pack(float v0, float v1) {
    return __byte_perm(__float_as_uint(v0), __float_as_uint(v1), 0x7632);
}
// lo = rn-bf16 of remainders, packed (elem0 low half)
__device__ __forceinline__ unsigned lo_pack(float v0, float v1) {
    float l0 = v0 - __uint_as_float(__float_as_uint(v0) & 0xFFFF0000u);
    float l1 = v1 - __uint_as_float(__float_as_uint(v1) & 0xFFFF0000u);
    unsigned w;
    asm("cvt.rn.satfinite.bf16x2.f32 %0, %1, %2;" : "=r"(w) : "f"(l1), "f"(l0));
    return w;
}
__device__ __forceinline__ void split_pair(float v0, float v1,
                                           unsigned& hi_word, unsigned& lo_word) {
    hi_word = hi_pack(v0, v1);
    lo_word = lo_pack(v0, v1);
}
__device__ __forceinline__ void quat_rotate(float w, float x, float y, float z,
                                            float vx, float vy, float vz,
                                            float& ox, float& oy, float& oz) {
    float n = sqrtf(w * w + x * x + y * y + z * z);
    float inv = 1.0f / (n + 1e-8f);
    w *= inv; x *= inv; y *= inv; z *= inv;
    float xx = x * x, yy = y * y, zz = z * z;
    float xy = x * y, xz = x * z, yz = y * z;
    float wx = w * x, wy = w * y, wz = w * z;
    ox = (1.f - 2.f * (yy + zz)) * vx + 2.f * (xy - wz) * vy + 2.f * (xz + wy) * vz;
    oy = 2.f * (xy + wz) * vx + (1.f - 2.f * (xx + zz)) * vy + 2.f * (yz - wx) * vz;
    oz = 2.f * (xz - wy) * vx + 2.f * (yz + wx) * vy + (1.f - 2.f * (xx + yy)) * vz;
}
__device__ __forceinline__ void ldsm_x4(unsigned* r, uint32_t addr) {
    asm volatile("ldmatrix.sync.aligned.m8n8.x4.shared.b16 {%0,%1,%2,%3}, [%4];"
                 : "=r"(r[0]), "=r"(r[1]), "=r"(r[2]), "=r"(r[3]) : "r"(addr));
}
__device__ __forceinline__ void mma16816(float* c, const unsigned* a, const unsigned* b) {
    asm volatile("mma.sync.aligned.m16n8k16.row.col.f32.bf16.bf16.f32 "
                 "{%0,%1,%2,%3}, {%4,%5,%6,%7}, {%8,%9}, {%0,%1,%2,%3};"
                 : "+f"(c[0]), "+f"(c[1]), "+f"(c[2]), "+f"(c[3])
                 : "r"(a[0]), "r"(a[1]), "r"(a[2]), "r"(a[3]), "r"(b[0]), "r"(b[1]));
}

// ---------------------------------------------------------------------------
// Kernel A (merged): blocks 0..255   -> per-(b,t) centroid + base (k-split x4)
//                    blocks 256..271 -> W2 -> bf16 hi/lo image conversion
//                    block  272      -> [Wt|Wr] -> B3 hi/lo fragments image
// Block = 1024 threads.
// ---------------------------------------------------------------------------
__global__ void __launch_bounds__(1024) prep_kernel(
    const float* __restrict__ sf, const float* __restrict__ trans,
    const float* __restrict__ W1, const float* __restrict__ b1,
    const float* __restrict__ W2,
    const float* __restrict__ Wt, const float* __restrict__ Wr)
{
    const int t = threadIdx.x;

    if (blockIdx.x >= BT_N) {
        int cb = blockIdx.x - BT_N;
        if (cb < 16) {
            // ---- W2 conversion: 16 blocks x 1024 threads = 16384 items ----
            int idx = cb * 1024 + t;
            int n  = idx & 127;            // fast -> coalesced W2 loads
            int kp = idx >> 7;             // 0..127
            int k0 = kp * 2;
            float w0 = W2[k0 * HID + n];
            float w1 = W2[(k0 + 1) * HID + n];
            unsigned hw, lw;
            split_pair(w0, w1, hw, lw);
            g_Bhi[n * 128 + kp] = hw;
            g_Blo[n * 128 + kp] = lw;
        } else if (t < 512) {
            // ---- B3 = [Wt|Wr|0|0] conversion: 8 n x 64 kpairs ----
            int n  = t >> 6;               // 0..7
            int kp = t & 63;               // 0..63
            int k0 = kp * 2;
            float w0 = 0.f, w1 = 0.f;
            if (n < 3)      { w0 = Wt[k0 * 3 + n];       w1 = Wt[(k0 + 1) * 3 + n]; }
            else if (n < 6) { w0 = Wr[k0 * 3 + (n - 3)]; w1 = Wr[(k0 + 1) * 3 + (n - 3)]; }
            unsigned hw, lw;
            split_pair(w0, w1, hw, lw);
            g_B3hi[n * 64 + kp] = hw;
            g_B3lo[n * 64 + kp] = lw;
        }
        return;
    }

    __shared__ float sfs[DIM];
    __shared__ float part[1024];
    __shared__ float red0[1024], red1[1024], red2[1024];

    const int bt = blockIdx.x;
    if (t < DIM) sfs[t] = sf[bt * DIM + t];

    // centroid: 512 rows
    float sx = 0.f, sy = 0.f, sz = 0.f;
    if (t < RPT) {
        const float* p = trans + ((size_t)bt * RPT + t) * 3;
        sx = p[0]; sy = p[1]; sz = p[2];
    }
    red0[t] = sx; red1[t] = sy; red2[t] = sz;
    __syncthreads();
    for (int s = 512; s > 0; s >>= 1) {
        if (t < s) { red0[t] += red0[t+s]; red1[t] += red1[t+s]; red2[t] += red2[t+s]; }
        __syncthreads();
    }
    if (t == 0) {
        g_centroid[bt*3+0] = red0[0] * (1.0f/RPT);
        g_centroid[bt*3+1] = red1[0] * (1.0f/RPT);
        g_centroid[bt*3+2] = red2[0] * (1.0f/RPT);
    }

    // base: thread (c = t>>8, j = t&255) sums k in [64c, 64c+64)
    {
        const int c = t >> 8, j = t & 255;
        const float* wp = W1 + (size_t)(c * 64) * DIM + j;
        const float* sp = sfs + c * 64;
        float acc = 0.f;
        #pragma unroll 8
        for (int k = 0; k < 64; k++) acc += sp[k] * wp[k * DIM];
        part[t] = acc;
    }
    __syncthreads();
    if (t < DIM) {
        g_base[bt * DIM + t] = b1[t] + part[t] + part[256 + t] + part[512 + t] + part[768 + t];
    }
}

// ---------------------------------------------------------------------------
// Kernel B: fused head, GEMM2 via mma.sync bf16x3, phase-3 heads via MMA.
// Grid (8,256), 256 threads (8 warps, 2m x 4n), 2 CTAs/SM.
// Phase 1 split into per-K-quarter chunks interleaved with the mainloop.
// ---------------------------------------------------------------------------
__global__ void __launch_bounds__(HTHR, 2) head_kernel(
    const float* __restrict__ quat, const float* __restrict__ trans,
    const float* __restrict__ W1, const float* __restrict__ b2,
    const float* __restrict__ btp, const float* __restrict__ brp,
    float* __restrict__ out)
{
    extern __shared__ char smp[];
    unsigned* smw = (unsigned*)smp;
    uint32_t sb = smem_u32(smp);

    float* misc   = (float*)smp + MISC_W;
    float* base_s = misc + MF_BASE;
    float* w1b    = misc + MF_W1B;
    float* quat_s = misc + MF_QUAT;
    float* lrp_s  = misc + MF_LRP;
    float* b2_s   = misc + MF_B2;
    float* btbr   = misc + MF_BTBR;
    float* part3  = (float*)smp + B_HI_W;            // overlays B after GEMM: [4][64][9]
    float* stage  = (float*)smp;                     // overlays A after GEMM

    const int t    = threadIdx.x;
    const int lane = t & 31;
    const int wid  = t >> 5;
    const int bt   = blockIdx.y;
    const int r0   = blockIdx.x * MROWS;

    // ---- prefetch B k-quarter 0 via cp.async ----
    #pragma unroll
    for (int i = t; i < 2048; i += HTHR) {
        int img = i >> 10;                // 0 = hi, 1 = lo
        int j = i & 1023, n = j >> 3, s = j & 7;
        uint32_t dst = sb + (uint32_t)((img ? B_LO_W : B_HI_W) + n * B_STRIDE_W + s * 4) * 4u;
        const uint4* src = ((const uint4*)(img ? g_Blo : g_Bhi)) + n * 32 + s;
        cp_async16(dst, src);
    }
    asm volatile("cp.async.commit_group;" ::: "memory");

    // ---- cooperative loads ----
    base_s[t] = g_base[bt * DIM + t];
    #pragma unroll
    for (int i = t; i < 3 * DIM; i += HTHR) w1b[i] = W1[DIM * DIM + i];
    quat_s[t] = quat[((size_t)bt * RPT + r0) * 4 + t];      // 64 rows * 4 = 256
    if (t < HID) b2_s[t] = b2[t];
    if (t < 3) { btbr[t] = btp[t]; btbr[4 + t] = brp[t]; }
    __syncthreads();

    // ---- local_rel_pos (conjugate rotation), 64 rows ----
    if (t < MROWS) {
        const float* tp = trans + ((size_t)bt * RPT + r0 + t) * 3;
        float vx = tp[0] - g_centroid[bt*3+0];
        float vy = tp[1] - g_centroid[bt*3+1];
        float vz = tp[2] - g_centroid[bt*3+2];
        float qw = quat_s[t*4+0], qx = quat_s[t*4+1], qy = quat_s[t*4+2], qz = quat_s[t*4+3];
        float o0, o1, o2;
        quat_rotate(qw, -qx, -qy, -qz, vx, vy, vz, o0, o1, o2);
        lrp_s[t*3+0] = o0; lrp_s[t*3+1] = o1; lrp_s[t*3+2] = o2;
    }
    __syncthreads();

    // ---- phase-1 chunk: A k-quarter qc -> bf16 hi/lo images (f32x2 math) ----
    // thread -> kp = (t&31) + 32*qc, rows rh*8..rh*8+7 (rh = t>>5)
    #define PHASE1_CHUNK(qc) do {                                              \
        int kp_ = (t & 31) + 32 * (qc);                                        \
        int rh_ = t >> 5;                                                      \
        int k0_ = kp_ * 2;                                                     \
        ull bb_ = pk2(base_s[k0_], base_s[k0_ + 1]);                           \
        ull wa_ = pk2(w1b[k0_], w1b[k0_ + 1]);                                 \
        ull wb_ = pk2(w1b[256 + k0_], w1b[256 + k0_ + 1]);                     \
        ull wc_ = pk2(w1b[512 + k0_], w1b[512 + k0_ + 1]);                     \
        ull zero_ = pk2(0.f, 0.f);                                             \
        ull c1_ = pk2(0.7978845608028654f, 0.7978845608028654f);               \
        ull c2_ = pk2(0.035677408136300125f, 0.035677408136300125f);           \
        ull hp_ = pk2(0.5f, 0.5f);                                             \
        _Pragma("unroll")                                                      \
        for (int r_ = 0; r_ < 8; r_++) {                                       \
            int row_ = rh_ * 8 + r_;                                           \
            float l0_ = lrp_s[row_*3+0], l1_ = lrp_s[row_*3+1], l2_ = lrp_s[row_*3+2]; \
            ull v_ = fma2(pk2(l0_, l0_), wa_, bb_);                            \
            v_ = fma2(pk2(l1_, l1_), wb_, v_);                                 \
            v_ = fma2(pk2(l2_, l2_), wc_, v_);                                 \
            ull t2_ = fma2(v_, v_, zero_);                                     \
            ull t3_ = fma2(t2_, v_, zero_);                                    \
            ull u_ = fma2(t3_, c2_, fma2(v_, c1_, zero_));                     \
            float u0_, u1_; upk2(u_, u0_, u1_);                                \
            ull th_ = pk2(fast_tanh(u0_), fast_tanh(u1_));                     \
            ull hv_ = fma2(v_, hp_, zero_);                                    \
            ull res_ = fma2(hv_, th_, hv_);                                    \
            float v0_, v1_; upk2(res_, v0_, v1_);                              \
            unsigned hw_, lw_; split_pair(v0_, v1_, hw_, lw_);                 \
            int w_ = row_ * A_STRIDE_W + kp_;                                  \
            smw[A_HI_W + w_] = hw_;                                            \
            smw[A_LO_W + w_] = lw_;                                            \
        }                                                                      \
    } while (0)

    PHASE1_CHUNK(0);

    // ---- GEMM2: C[64x128] = h1 @ W2, bf16x3 via mma.sync ----
    const int wm = wid >> 2;          // 0..1 (m half, 32 rows)
    const int wn = wid & 3;           // 0..3 (n quarter, 32 cols)

    float acc[2][4][4];
    #pragma unroll
    for (int i = 0; i < 2; i++)
        #pragma unroll
        for (int j = 0; j < 4; j++)
            #pragma unroll
            for (int k = 0; k < 4; k++) acc[i][j][k] = 0.f;

    // A ldmatrix lane addresses (bytes)
    uint32_t aAddrHi = sb + ((uint32_t)(wm*32 + (lane & 15)) * A_STRIDE_W
                             + ((lane >> 4) << 2)) * 4u;
    uint32_t aAddrLo = aAddrHi + A_LO_W * 4u;
    // B ldmatrix x4 lane addresses: serves two n-tiles per load
    const int bg = lane >> 3, bl8 = lane & 7;
    uint32_t bAddrHi = sb + (uint32_t)(B_HI_W
                             + (uint32_t)(wn*32 + ((bg & 2) << 2) + bl8) * B_STRIDE_W
                             + ((bg & 1) << 2)) * 4u;
    uint32_t bAddrLo = bAddrHi + (uint32_t)(B_LO_W - B_HI_W) * 4u;

    #pragma unroll 1
    for (int q = 0; q < 4; q++) {
        asm volatile("cp.async.wait_group 0;" ::: "memory");
        __syncthreads();              // B quarter q ready + A chunk q written

        #pragma unroll
        for (int ks = 0; ks < 4; ks++) {
            unsigned ah[2][4], al[2][4], bh4[2][4], bl4[2][4];
            uint32_t aCol = (uint32_t)(q * 4 + ks) * 32u;     // bytes
            #pragma unroll
            for (int mt = 0; mt < 2; mt++) {
                uint32_t off = (uint32_t)mt * (16 * A_STRIDE_W * 4) + aCol;
                ldsm_x4(ah[mt], aAddrHi + off);
                ldsm_x4(al[mt], aAddrLo + off);
            }
            #pragma unroll
            for (int np = 0; np < 2; np++) {
                uint32_t off = (uint32_t)np * (16 * B_STRIDE_W * 4) + (uint32_t)ks * 32u;
                ldsm_x4(bh4[np], bAddrHi + off);
                ldsm_x4(bl4[np], bAddrLo + off);
            }
            // breadth-first passes: same-acc MMA distance = 8
            #pragma unroll
            for (int mt = 0; mt < 2; mt++)
                #pragma unroll
                for (int nt = 0; nt < 4; nt++)
                    mma16816(acc[mt][nt], ah[mt], &bh4[nt >> 1][(nt & 1) * 2]);
            #pragma unroll
            for (int mt = 0; mt < 2; mt++)
                #pragma unroll
                for (int nt = 0; nt < 4; nt++)
                    mma16816(acc[mt][nt], ah[mt], &bl4[nt >> 1][(nt & 1) * 2]);
            #pragma unroll
            for (int mt = 0; mt < 2; mt++)
                #pragma unroll
                for (int nt = 0; nt < 4; nt++)
                    mma16816(acc[mt][nt], al[mt], &bh4[nt >> 1][(nt & 1) * 2]);
        }
        __syncthreads();              // all LDSM reads of B quarter q done

        if (q < 3) {
            // async copy of B quarter q+1 (overlaps the phase-1 chunk below)
            #pragma unroll
            for (int i = t; i < 2048; i += HTHR) {
                int img = i >> 10;
                int j = i & 1023, n = j >> 3, s = j & 7;
                uint32_t dst = sb + (uint32_t)((img ? B_LO_W : B_HI_W)
                                               + n * B_STRIDE_W + s * 4) * 4u;
                const uint4* src = ((const uint4*)(img ? g_Blo : g_Bhi))
                                   + n * 32 + (q + 1) * 8 + s;
                cp_async16(dst, src);
            }
            asm volatile("cp.async.commit_group;" ::: "memory");
            // phase-1 for A k-quarter q+1 while the copy flies
            if (q == 0) PHASE1_CHUNK(1);
            else if (q == 1) PHASE1_CHUNK(2);
            else PHASE1_CHUNK(3);
        }
    }

    // ---- epilogue: gelu in regs, then phase-3 heads via MMA (no h2 smem) ----
    const int q3 = lane & 3, g3 = lane >> 2;

    // gelu(acc + b2) in place
    #pragma unroll
    for (int mt = 0; mt < 2; mt++)
        #pragma unroll
        for (int nt = 0; nt < 4; nt++) {
            int col = wn*32 + nt*8 + 2*q3;
            float bA = b2_s[col], bB = b2_s[col+1];
            acc[mt][nt][0] = gelu_tanh(acc[mt][nt][0] + bA);
            acc[mt][nt][1] = gelu_tanh(acc[mt][nt][1] + bB);
            acc[mt][nt][2] = gelu_tanh(acc[mt][nt][2] + bA);
            acc[mt][nt][3] = gelu_tanh(acc[mt][nt][3] + bB);
        }

    // B3 fragments (constant per warp): [Wt|Wr|0|0] hi/lo, k-slice = h2 cols of this warp
    unsigned b3h[2][2], b3l[2][2];
    {
        int n3 = lane >> 2;                     // 0..7 (col of B3)
        #pragma unroll
        for (int kk = 0; kk < 2; kk++) {
            int base = n3 * 64 + ((wn*32 + kk*16) >> 1) + q3;
            b3h[kk][0] = g_B3hi[base];     b3h[kk][1] = g_B3hi[base + 4];
            b3l[kk][0] = g_B3lo[base];     b3l[kk][1] = g_B3lo[base + 4];
        }
    }

    // C3 partials: rows of this warp x 8 cols, k-summed over this warp's 32 h2-cols
    float c3[2][4];
    #pragma unroll
    for (int mt = 0; mt < 2; mt++) {
        c3[mt][0] = c3[mt][1] = c3[mt][2] = c3[mt][3] = 0.f;
        #pragma unroll
        for (int kk = 0; kk < 2; kk++) {
            unsigned aH[4], aL[4];
            const float* c0 = acc[mt][2*kk];        // k 2q,2q+1 block
            const float* c1 = acc[mt][2*kk + 1];    // k 2q+8,2q+9 block
            aH[0] = hi_pack(c0[0], c0[1]);  aH[1] = hi_pack(c0[2], c0[3]);
            aH[2] = hi_pack(c1[0], c1[1]);  aH[3] = hi_pack(c1[2], c1[3]);
            aL[0] = lo_pack(c0[0], c0[1]);  aL[1] = lo_pack(c0[2], c0[3]);
            aL[2] = lo_pack(c1[0], c1[1]);  aL[3] = lo_pack(c1[2], c1[3]);
            mma16816(c3[mt], aH, b3h[kk]);
            mma16816(c3[mt], aH, b3l[kk]);
            mma16816(c3[mt], aL, b3h[kk]);
        }
    }

    __syncthreads();                   // all mainloop smem reads done; B region reusable

    // write partials: part3[wn][row][9]
    #pragma unroll
    for (int mt = 0; mt < 2; mt++) {
        int row0 = wm*32 + mt*16 + g3;
        part3[(wn*64 + row0) * 9 + 2*q3]     = c3[mt][0];
        part3[(wn*64 + row0) * 9 + 2*q3 + 1] = c3[mt][1];
        part3[(wn*64 + row0 + 8) * 9 + 2*q3]     = c3[mt][2];
        part3[(wn*64 + row0 + 8) * 9 + 2*q3 + 1] = c3[mt][3];
    }
    __syncthreads();

    // ---- reduce partials + quaternion algebra (64 threads, 1 per row) ----
    if (t < MROWS) {
        float s[6];
        #pragma unroll
        for (int c = 0; c < 6; c++)
            s[c] = part3[t*9 + c] + part3[(64 + t)*9 + c]
                 + part3[(128 + t)*9 + c] + part3[(192 + t)*9 + c];

        float tv0 = s[0] + btbr[0], tv1 = s[1] + btbr[1], tv2 = s[2] + btbr[2];
        float rv0 = (s[3] + btbr[4]) * 0.1f;
        float rv1 = (s[4] + btbr[5]) * 0.1f;
        float rv2 = (s[5] + btbr[6]) * 0.1f;
        float qw = quat_s[t*4+0], qx = quat_s[t*4+1];
        float qy = quat_s[t*4+2], qz = quat_s[t*4+3];
        float wx, wy, wz;
        quat_rotate(qw, qx, qy, qz, tv0, tv1, tv2, wx, wy, wz);
        float qvw = 0.5f * (-qx*rv0 - qy*rv1 - qz*rv2);
        float qvx = 0.5f * ( qw*rv0 + qy*rv2 - qz*rv1);
        float qvy = 0.5f * ( qw*rv1 - qx*rv2 + qz*rv0);
        float qvz = 0.5f * ( qw*rv2 + qx*rv1 - qy*rv0);
        float* st = stage + t * 7;
        st[0]=qvw; st[1]=qvx; st[2]=qvy; st[3]=qvz; st[4]=wx; st[5]=wy; st[6]=wz;
    }
    __syncthreads();

    // coalesced store: 448 contiguous floats per CTA
    {
        float* obase = out + ((size_t)bt * RPT + r0) * 7;
        obase[t] = stage[t];
        if (t < 448 - HTHR) obase[t + HTHR] = stage[t + HTHR];
    }
}

// ---------------------------------------------------------------------------
extern "C" void kernel_launch(void* const* d_in, const int* in_sizes, int n_in,
                              void* d_out, int out_size) {
    const float* sf    = (const float*)d_in[0];
    const float* quat  = (const float*)d_in[1];
    const float* trans = (const float*)d_in[2];
    const float* W1    = (const float*)d_in[3];
    const float* b1    = (const float*)d_in[4];
    const float* W2    = (const float*)d_in[5];
    const float* b2    = (const float*)d_in[6];
    const float* Wt    = (const float*)d_in[7];
    const float* btp   = (const float*)d_in[8];
    const float* Wr    = (const float*)d_in[9];
    const float* brp   = (const float*)d_in[10];
    float* out = (float*)d_out;

    cudaFuncSetAttribute(head_kernel, cudaFuncAttributeMaxDynamicSharedMemorySize,
                         SMEM_BYTES);

    prep_kernel<<<BT_N + 17, 1024>>>(sf, trans, W1, b1, W2, Wt, Wr);

    dim3 grid(RPT / MROWS, BT_N);    // (8, 256)
    head_kernel<<<grid, HTHR, SMEM_BYTES>>>(quat, trans, W1, b2, btp, brp, out);
}